// round 1
// baseline (speedup 1.0000x reference)
#include <cuda_runtime.h>
#include <math.h>

// ---------------- scratch (device globals; no allocation allowed) -----------
__device__ float g_ln1[4096 * 1024];
__device__ float g_qkv[4096 * 3072];
__device__ float g_att[4096 * 1024];
__device__ float g_x1 [4096 * 1024];
__device__ float g_ln2[4096 * 1024];
__device__ float g_up [4096 * 4096];

// ---------------- LayerNorm: one block per row of 1024 ---------------------
__global__ __launch_bounds__(256) void ln_kernel(const float* __restrict__ x,
                                                 const float* __restrict__ g,
                                                 const float* __restrict__ b,
                                                 float* __restrict__ y) {
    int row = blockIdx.x;
    int tid = threadIdx.x;  // 256, each handles one float4 (1024 floats/row)
    const float4* xr = (const float4*)(x + (size_t)row * 1024);
    float4 v = xr[tid];
    float s  = v.x + v.y + v.z + v.w;
    float sq = v.x * v.x + v.y * v.y + v.z * v.z + v.w * v.w;
    #pragma unroll
    for (int off = 16; off; off >>= 1) {
        s  += __shfl_xor_sync(0xFFFFFFFFu, s,  off);
        sq += __shfl_xor_sync(0xFFFFFFFFu, sq, off);
    }
    __shared__ float ss[8], ssq[8];
    int w = tid >> 5, ln = tid & 31;
    if (ln == 0) { ss[w] = s; ssq[w] = sq; }
    __syncthreads();
    float tot = 0.f, totq = 0.f;
    #pragma unroll
    for (int i = 0; i < 8; i++) { tot += ss[i]; totq += ssq[i]; }
    float mu   = tot * (1.f / 1024.f);
    float var  = totq * (1.f / 1024.f) - mu * mu;
    float rstd = rsqrtf(var + 1e-5f);
    float4 gg = ((const float4*)g)[tid];
    float4 bb = ((const float4*)b)[tid];
    float4 o;
    o.x = (v.x - mu) * rstd * gg.x + bb.x;
    o.y = (v.y - mu) * rstd * gg.y + bb.y;
    o.z = (v.z - mu) * rstd * gg.z + bb.z;
    o.w = (v.w - mu) * rstd * gg.w + bb.w;
    ((float4*)(y + (size_t)row * 1024))[tid] = o;
}

// ---------------- GEMM: C[M,N] = A[M,K] * B[N,K]^T + bias (+res) (gelu) ----
// 128x128 block tile, BK=8, 256 threads, 8x8 micro-tile per thread.
__device__ __forceinline__ float gelu_f(float t) {
    return 0.5f * t * (1.f + tanhf(0.7978845608028654f * (t + 0.044715f * t * t * t)));
}

template <bool GELU, bool RES>
__global__ __launch_bounds__(256) void gemm_kernel(
    const float* __restrict__ A, const float* __restrict__ B,
    const float* __restrict__ bias, const float* __restrict__ res,
    float* __restrict__ C, int M, int N, int K)
{
    __shared__ float As[8][128];
    __shared__ float Bs[8][128];
    int tid = threadIdx.x;
    int m0 = blockIdx.y * 128, n0 = blockIdx.x * 128;

    int lr = tid >> 1;          // 0..127 (row within tile)
    int lq = (tid & 1) * 4;     // float4 slot within BK=8
    const float* Ag = A + (size_t)(m0 + lr) * K + lq;
    const float* Bg = B + (size_t)(n0 + lr) * K + lq;

    int ty = tid >> 4, tx = tid & 15;

    float acc[8][8];
    #pragma unroll
    for (int i = 0; i < 8; i++)
        #pragma unroll
        for (int j = 0; j < 8; j++) acc[i][j] = 0.f;

    for (int k0 = 0; k0 < K; k0 += 8) {
        float4 a4 = *(const float4*)(Ag + k0);
        float4 b4 = *(const float4*)(Bg + k0);
        __syncthreads();
        As[lq + 0][lr] = a4.x; As[lq + 1][lr] = a4.y;
        As[lq + 2][lr] = a4.z; As[lq + 3][lr] = a4.w;
        Bs[lq + 0][lr] = b4.x; Bs[lq + 1][lr] = b4.y;
        Bs[lq + 2][lr] = b4.z; Bs[lq + 3][lr] = b4.w;
        __syncthreads();
        #pragma unroll
        for (int k = 0; k < 8; k++) {
            float ra[8], rb[8];
            #pragma unroll
            for (int i = 0; i < 8; i++) ra[i] = As[k][ty * 8 + i];
            #pragma unroll
            for (int j = 0; j < 8; j++) rb[j] = Bs[k][tx * 8 + j];
            #pragma unroll
            for (int i = 0; i < 8; i++)
                #pragma unroll
                for (int j = 0; j < 8; j++)
                    acc[i][j] = fmaf(ra[i], rb[j], acc[i][j]);
        }
    }

    const float* bp = bias + n0 + tx * 8;
    #pragma unroll
    for (int i = 0; i < 8; i++) {
        int rg = m0 + ty * 8 + i;
        float* cr = C + (size_t)rg * N + n0 + tx * 8;
        const float* rr = res + (size_t)rg * N + n0 + tx * 8;  // only read if RES
        #pragma unroll
        for (int j = 0; j < 8; j++) {
            float v = acc[i][j] + bp[j];
            if (RES)  v += rr[j];
            if (GELU) v = gelu_f(v);
            cr[j] = v;
        }
    }
}

// ---------------- Causal attention (flash-style, fp32) ----------------------
// Grid: (qblocks=16, H=16, B=2). Block: 128 threads; thread owns one query row.
// KT=32 key tile in smem; per-thread scores staged in padded smem.
__global__ __launch_bounds__(128) void attn_kernel(const float* __restrict__ qkv,
                                                   float* __restrict__ out) {
    __shared__ float Ks[32][64];
    __shared__ float Vs[32][64];
    __shared__ float Ss[128][33];

    int tid = threadIdx.x;
    int qb = blockIdx.x, h = blockIdx.y, bb = blockIdx.z;
    int qidx = qb * 128 + tid;

    const float* base = qkv + (size_t)bb * 2048 * 3072;
    const float* qrow = base + (size_t)qidx * 3072 + h * 64;

    float q[64];
    #pragma unroll
    for (int d = 0; d < 64; d++) q[d] = qrow[d] * 0.125f;  // fold 1/sqrt(64)
    float o[64];
    #pragma unroll
    for (int d = 0; d < 64; d++) o[d] = 0.f;
    float m = -INFINITY, l = 0.f;

    int ntiles = (qb + 1) * 4;  // keys up to (qb+1)*128, tiles of 32
    for (int t = 0; t < ntiles; t++) {
        int k0 = t * 32;
        __syncthreads();
        // load K,V tiles: 32 rows x 16 float4 each
        for (int i = tid; i < 32 * 16; i += 128) {
            int r = i >> 4, c = i & 15;
            const float* kr = base + (size_t)(k0 + r) * 3072 + 1024 + h * 64;
            const float* vr = base + (size_t)(k0 + r) * 3072 + 2048 + h * 64;
            ((float4*)Ks[r])[c] = ((const float4*)kr)[c];
            ((float4*)Vs[r])[c] = ((const float4*)vr)[c];
        }
        __syncthreads();

        float tmax = -INFINITY;
        bool dg = (k0 + 31 > qidx);
        for (int kk = 0; kk < 32; kk++) {
            float s = 0.f;
            #pragma unroll
            for (int d = 0; d < 64; d++) s = fmaf(q[d], Ks[kk][d], s);
            if (dg && (k0 + kk > qidx)) s = -INFINITY;
            Ss[tid][kk] = s;
            tmax = fmaxf(tmax, s);
        }
        float mn = fmaxf(m, tmax);
        float corr = __expf(m - mn);  // m=-inf on first tile -> 0
        l *= corr;
        #pragma unroll
        for (int d = 0; d < 64; d++) o[d] *= corr;
        for (int kk = 0; kk < 32; kk++) {
            float p = __expf(Ss[tid][kk] - mn);
            l += p;
            #pragma unroll
            for (int d = 0; d < 64; d++) o[d] = fmaf(p, Vs[kk][d], o[d]);
        }
        m = mn;
    }

    float inv = 1.f / l;
    float* orow = out + ((size_t)bb * 2048 + qidx) * 1024 + h * 64;
    #pragma unroll
    for (int c = 0; c < 16; c++) {
        float4 v = make_float4(o[4 * c] * inv, o[4 * c + 1] * inv,
                               o[4 * c + 2] * inv, o[4 * c + 3] * inv);
        ((float4*)orow)[c] = v;
    }
}

// ---------------- launch ----------------------------------------------------
extern "C" void kernel_launch(void* const* d_in, const int* in_sizes, int n_in,
                              void* d_out, int out_size) {
    const float* x      = (const float*)d_in[0];
    const float* ln1_g  = (const float*)d_in[1];
    const float* ln1_b  = (const float*)d_in[2];
    const float* W_attn = (const float*)d_in[3];
    const float* b_attn = (const float*)d_in[4];
    const float* W_proj = (const float*)d_in[5];
    const float* b_proj = (const float*)d_in[6];
    const float* ln2_g  = (const float*)d_in[7];
    const float* ln2_b  = (const float*)d_in[8];
    const float* W_up   = (const float*)d_in[9];
    const float* b_up   = (const float*)d_in[10];
    const float* W_down = (const float*)d_in[11];
    const float* b_down = (const float*)d_in[12];
    float* out = (float*)d_out;

    float *ln1, *qkv, *att, *x1, *ln2, *up;
    cudaGetSymbolAddress((void**)&ln1, g_ln1);
    cudaGetSymbolAddress((void**)&qkv, g_qkv);
    cudaGetSymbolAddress((void**)&att, g_att);
    cudaGetSymbolAddress((void**)&x1,  g_x1);
    cudaGetSymbolAddress((void**)&ln2, g_ln2);
    cudaGetSymbolAddress((void**)&up,  g_up);

    // 1. LN1
    ln_kernel<<<4096, 256>>>(x, ln1_g, ln1_b, ln1);
    // 2. QKV = ln1 @ W_attn^T + b_attn   [4096,3072]
    gemm_kernel<false, false><<<dim3(3072 / 128, 4096 / 128), 256>>>(
        ln1, W_attn, b_attn, nullptr, qkv, 4096, 3072, 1024);
    // 3. causal attention -> att [4096,1024]
    attn_kernel<<<dim3(16, 16, 2), 128>>>(qkv, att);
    // 4. x1 = x + att @ W_proj^T + b_proj
    gemm_kernel<false, true><<<dim3(1024 / 128, 4096 / 128), 256>>>(
        att, W_proj, b_proj, x, x1, 4096, 1024, 1024);
    // 5. LN2
    ln_kernel<<<4096, 256>>>(x1, ln2_g, ln2_b, ln2);
    // 6. up = gelu(ln2 @ W_up^T + b_up)  [4096,4096]
    gemm_kernel<true, false><<<dim3(4096 / 128, 4096 / 128), 256>>>(
        ln2, W_up, b_up, nullptr, up, 4096, 4096, 1024);
    // 7. out = x1 + up @ W_down^T + b_down
    gemm_kernel<false, true><<<dim3(1024 / 128, 4096 / 128), 256>>>(
        up, W_down, b_down, x1, out, 4096, 1024, 4096);
}

// round 3
// speedup vs baseline: 2.4060x; 2.4060x over previous
#include <cuda_runtime.h>
#include <math.h>
#include <stdint.h>

// ===================== scratch (device globals; no alloc allowed) ===========
__device__ float g_ln1[4096 * 1024];
__device__ float g_qkv[4096 * 3072];
__device__ float g_att[4096 * 1024];
__device__ float g_x1 [4096 * 1024];
__device__ float g_ln2[4096 * 1024];
__device__ float g_up [4096 * 4096];
__device__ float g_wattn[3 * 1024 * 1024];
__device__ float g_wproj[1024 * 1024];
__device__ float g_wup  [4 * 1024 * 1024];
__device__ float g_wdown[4 * 1024 * 1024];

// ===================== helpers ==============================================
__device__ __forceinline__ float tf32_rn(float x) {
    uint32_t u = __float_as_uint(x);
    asm("cvt.rna.tf32.f32 %0, %1;" : "=r"(u) : "r"(u));
    return __uint_as_float(u);
}

__device__ __forceinline__ void cp16(uint32_t saddr, const float* g) {
    asm volatile("cp.async.cg.shared.global [%0], [%1], 16;"
                 :: "r"(saddr), "l"(__cvta_generic_to_global(g)));
}

__device__ __forceinline__ void ldsm4(uint32_t* r, uint32_t addr) {
    asm volatile("ldmatrix.sync.aligned.m8n8.x4.shared.b16 {%0,%1,%2,%3}, [%4];"
                 : "=r"(r[0]), "=r"(r[1]), "=r"(r[2]), "=r"(r[3]) : "r"(addr));
}

__device__ __forceinline__ void mma_tf32(float* d, const uint32_t* a, const uint32_t* b) {
    asm volatile("mma.sync.aligned.m16n8k8.row.col.f32.tf32.tf32.f32 "
                 "{%0,%1,%2,%3}, {%4,%5,%6,%7}, {%8,%9}, {%0,%1,%2,%3};"
                 : "+f"(d[0]), "+f"(d[1]), "+f"(d[2]), "+f"(d[3])
                 : "r"(a[0]), "r"(a[1]), "r"(a[2]), "r"(a[3]), "r"(b[0]), "r"(b[1]));
}

__device__ __forceinline__ float gelu_f(float t) {
    return 0.5f * t * (1.f + tanhf(0.7978845608028654f * (t + 0.044715f * t * t * t)));
}

// ===================== tf32 weight converter ================================
__global__ __launch_bounds__(256) void cvt_tf32_kernel(const float4* __restrict__ in,
                                                       float4* __restrict__ out, int n4) {
    int i = blockIdx.x * 256 + threadIdx.x;
    if (i < n4) {
        float4 v = in[i];
        v.x = tf32_rn(v.x); v.y = tf32_rn(v.y);
        v.z = tf32_rn(v.z); v.w = tf32_rn(v.w);
        out[i] = v;
    }
}

// ===================== LayerNorm (tf32-rounded output) ======================
__global__ __launch_bounds__(256) void ln_kernel(const float* __restrict__ x,
                                                 const float* __restrict__ g,
                                                 const float* __restrict__ b,
                                                 float* __restrict__ y) {
    int row = blockIdx.x;
    int tid = threadIdx.x;
    const float4* xr = (const float4*)(x + (size_t)row * 1024);
    float4 v = xr[tid];
    float s  = v.x + v.y + v.z + v.w;
    float sq = v.x * v.x + v.y * v.y + v.z * v.z + v.w * v.w;
    #pragma unroll
    for (int off = 16; off; off >>= 1) {
        s  += __shfl_xor_sync(0xFFFFFFFFu, s,  off);
        sq += __shfl_xor_sync(0xFFFFFFFFu, sq, off);
    }
    __shared__ float ss[8], ssq[8];
    int w = tid >> 5, ln = tid & 31;
    if (ln == 0) { ss[w] = s; ssq[w] = sq; }
    __syncthreads();
    float tot = 0.f, totq = 0.f;
    #pragma unroll
    for (int i = 0; i < 8; i++) { tot += ss[i]; totq += ssq[i]; }
    float mu   = tot * (1.f / 1024.f);
    float var  = totq * (1.f / 1024.f) - mu * mu;
    float rstd = rsqrtf(var + 1e-5f);
    float4 gg = ((const float4*)g)[tid];
    float4 bb = ((const float4*)b)[tid];
    float4 o;
    o.x = tf32_rn((v.x - mu) * rstd * gg.x + bb.x);
    o.y = tf32_rn((v.y - mu) * rstd * gg.y + bb.y);
    o.z = tf32_rn((v.z - mu) * rstd * gg.z + bb.z);
    o.w = tf32_rn((v.w - mu) * rstd * gg.w + bb.w);
    ((float4*)(y + (size_t)row * 1024))[tid] = o;
}

// ===================== mma.sync TF32 GEMM ===================================
// C[M,N] = A[M,K] @ B[N,K]^T (+bias)(+res)(gelu)(round-to-tf32)
// CTA: 128x128 tile, BK=32, 256 threads (8 warps, warp tile 64x32).
#define BM 128
#define BN 128
#define BKG 32
// smem: A0 A1 B0 B1, each 128 rows x 128 bytes = 16KB
#define SM_BUF 16384
#define SMEM_BYTES (4 * SM_BUF)

__device__ __forceinline__ uint32_t swz(uint32_t row, uint32_t chunk, uint32_t xr) {
    // byte addr within 128B-row tile with SW128-style xor on the 16B chunk index
    return row * 128 + (((chunk) ^ xr) << 4);
}

template <bool GELU, bool RES, bool RND>
__global__ __launch_bounds__(256, 2) void gemm_mma(
    const float* __restrict__ A, const float* __restrict__ B,
    const float* __restrict__ bias, const float* __restrict__ res,
    float* __restrict__ C, int M, int N, int K)
{
    extern __shared__ char smem[];
    uint32_t sbase = (uint32_t)__cvta_generic_to_shared(smem);
    uint32_t sA[2] = { sbase,              sbase + SM_BUF };
    uint32_t sB[2] = { sbase + 2 * SM_BUF, sbase + 3 * SM_BUF };

    int tid  = threadIdx.x;
    int warp = tid >> 5, lane = tid & 31;
    int m0 = blockIdx.y * BM, n0 = blockIdx.x * BN;
    int wm = (warp & 1) * 64;      // 2 warps along M
    int wn = (warp >> 1) * 32;     // 4 warps along N

    // ldmatrix per-thread geometry
    int mat = lane >> 3, rowIn = lane & 7;
    int rA = wm + rowIn + 8 * (mat & 1);
    int cA = mat >> 1;                 // 0/1 -> +0/+16B within kstep
    int rB = wn + rowIn + 8 * (mat >> 1);
    int cB = mat & 1;

    // cp.async slots: tile = 128 rows x 8 chunks -> 1024 chunks, 4 per thread
    uint32_t offA[4]; const float* gA[4];
    uint32_t offB[4]; const float* gB[4];
    #pragma unroll
    for (int t = 0; t < 4; t++) {
        int idx = tid + t * 256;
        int r = idx >> 3, c = idx & 7;
        uint32_t o = swz(r, c, r & 7);
        offA[t] = o; offB[t] = o;
        gA[t] = A + (size_t)(m0 + r) * K + c * 4;
        gB[t] = B + (size_t)(n0 + r) * K + c * 4;
    }

    float acc[4][4][4];
    #pragma unroll
    for (int i = 0; i < 4; i++)
        #pragma unroll
        for (int j = 0; j < 4; j++)
            #pragma unroll
            for (int e = 0; e < 4; e++) acc[i][j][e] = 0.f;

    int NC = K / BKG;

    // prologue: load chunk 0 into buf 0
    #pragma unroll
    for (int t = 0; t < 4; t++) cp16(sA[0] + offA[t], gA[t]);
    #pragma unroll
    for (int t = 0; t < 4; t++) cp16(sB[0] + offB[t], gB[t]);
    asm volatile("cp.async.commit_group;" ::: "memory");

    for (int c = 0; c < NC; c++) {
        int buf = c & 1;
        if (c + 1 < NC) {
            int koff = (c + 1) * BKG;
            #pragma unroll
            for (int t = 0; t < 4; t++) cp16(sA[buf ^ 1] + offA[t], gA[t] + koff);
            #pragma unroll
            for (int t = 0; t < 4; t++) cp16(sB[buf ^ 1] + offB[t], gB[t] + koff);
            asm volatile("cp.async.commit_group;" ::: "memory");
            asm volatile("cp.async.wait_group 1;" ::: "memory");
        } else {
            asm volatile("cp.async.wait_group 0;" ::: "memory");
        }
        __syncthreads();

        uint32_t bA = sA[buf], bB = sB[buf];
        #pragma unroll
        for (int ks = 0; ks < 4; ks++) {
            uint32_t af[4][4], bf[2][4];
            #pragma unroll
            for (int i = 0; i < 4; i++)
                ldsm4(af[i], bA + swz((uint32_t)(rA + 16 * i), (uint32_t)(ks * 2 + cA), (uint32_t)rowIn));
            #pragma unroll
            for (int p = 0; p < 2; p++)
                ldsm4(bf[p], bB + swz((uint32_t)(rB + 16 * p), (uint32_t)(ks * 2 + cB), (uint32_t)rowIn));
            #pragma unroll
            for (int i = 0; i < 4; i++) {
                #pragma unroll
                for (int j = 0; j < 4; j++) {
                    // bf[p] regs: {b0 of ntile 2p, b1 of ntile 2p, b0 of 2p+1, b1 of 2p+1}
                    uint32_t bb[2] = { bf[j >> 1][(j & 1) * 2], bf[j >> 1][(j & 1) * 2 + 1] };
                    mma_tf32(acc[i][j], af[i], bb);
                }
            }
        }
        __syncthreads();
    }

    // epilogue
    #pragma unroll
    for (int i = 0; i < 4; i++) {
        int gr = m0 + wm + i * 16 + (lane >> 2);
        #pragma unroll
        for (int j = 0; j < 4; j++) {
            int gc = n0 + wn + j * 8 + (lane & 3) * 2;
            float2 bv = *(const float2*)(bias + gc);
            float v0 = acc[i][j][0] + bv.x, v1 = acc[i][j][1] + bv.y;
            float v2 = acc[i][j][2] + bv.x, v3 = acc[i][j][3] + bv.y;
            if (RES) {
                float2 r0 = *(const float2*)(res + (size_t)gr * N + gc);
                float2 r1 = *(const float2*)(res + (size_t)(gr + 8) * N + gc);
                v0 += r0.x; v1 += r0.y; v2 += r1.x; v3 += r1.y;
            }
            if (GELU) { v0 = gelu_f(v0); v1 = gelu_f(v1); v2 = gelu_f(v2); v3 = gelu_f(v3); }
            if (RND)  { v0 = tf32_rn(v0); v1 = tf32_rn(v1); v2 = tf32_rn(v2); v3 = tf32_rn(v3); }
            *(float2*)(C + (size_t)gr * N + gc)       = make_float2(v0, v1);
            *(float2*)(C + (size_t)(gr + 8) * N + gc) = make_float2(v2, v3);
        }
    }
}

// ===================== Causal attention (flash-style, fp32) =================
__global__ __launch_bounds__(128) void attn_kernel(const float* __restrict__ qkv,
                                                   float* __restrict__ out) {
    __shared__ float Ks[32][64];
    __shared__ float Vs[32][64];
    __shared__ float Ss[128][33];

    int tid = threadIdx.x;
    int qb = blockIdx.x, h = blockIdx.y, bb = blockIdx.z;
    int qidx = qb * 128 + tid;

    const float* base = qkv + (size_t)bb * 2048 * 3072;
    const float* qrow = base + (size_t)qidx * 3072 + h * 64;

    float q[64];
    #pragma unroll
    for (int d = 0; d < 64; d++) q[d] = qrow[d] * 0.125f;
    float o[64];
    #pragma unroll
    for (int d = 0; d < 64; d++) o[d] = 0.f;
    float m = -INFINITY, l = 0.f;

    int ntiles = (qb + 1) * 4;
    for (int t = 0; t < ntiles; t++) {
        int k0 = t * 32;
        __syncthreads();
        for (int i = tid; i < 32 * 16; i += 128) {
            int r = i >> 4, c = i & 15;
            const float* kr = base + (size_t)(k0 + r) * 3072 + 1024 + h * 64;
            const float* vr = base + (size_t)(k0 + r) * 3072 + 2048 + h * 64;
            ((float4*)Ks[r])[c] = ((const float4*)kr)[c];
            ((float4*)Vs[r])[c] = ((const float4*)vr)[c];
        }
        __syncthreads();

        float tmax = -INFINITY;
        bool dg = (k0 + 31 > qidx);
        for (int kk = 0; kk < 32; kk++) {
            float s = 0.f;
            #pragma unroll
            for (int d = 0; d < 64; d++) s = fmaf(q[d], Ks[kk][d], s);
            if (dg && (k0 + kk > qidx)) s = -INFINITY;
            Ss[tid][kk] = s;
            tmax = fmaxf(tmax, s);
        }
        float mn = fmaxf(m, tmax);
        float corr = __expf(m - mn);
        l *= corr;
        #pragma unroll
        for (int d = 0; d < 64; d++) o[d] *= corr;
        for (int kk = 0; kk < 32; kk++) {
            float p = __expf(Ss[tid][kk] - mn);
            l += p;
            #pragma unroll
            for (int d = 0; d < 64; d++) o[d] = fmaf(p, Vs[kk][d], o[d]);
        }
        m = mn;
    }

    float inv = 1.f / l;
    float* orow = out + ((size_t)bb * 2048 + qidx) * 1024 + h * 64;
    #pragma unroll
    for (int c = 0; c < 16; c++) {
        float4 v = make_float4(tf32_rn(o[4 * c] * inv), tf32_rn(o[4 * c + 1] * inv),
                               tf32_rn(o[4 * c + 2] * inv), tf32_rn(o[4 * c + 3] * inv));
        ((float4*)orow)[c] = v;
    }
}

// ===================== launch ===============================================
extern "C" void kernel_launch(void* const* d_in, const int* in_sizes, int n_in,
                              void* d_out, int out_size) {
    const float* x      = (const float*)d_in[0];
    const float* ln1_g  = (const float*)d_in[1];
    const float* ln1_b  = (const float*)d_in[2];
    const float* W_attn = (const float*)d_in[3];
    const float* b_attn = (const float*)d_in[4];
    const float* W_proj = (const float*)d_in[5];
    const float* b_proj = (const float*)d_in[6];
    const float* ln2_g  = (const float*)d_in[7];
    const float* ln2_b  = (const float*)d_in[8];
    const float* W_up   = (const float*)d_in[9];
    const float* b_up   = (const float*)d_in[10];
    const float* W_down = (const float*)d_in[11];
    const float* b_down = (const float*)d_in[12];
    float* out = (float*)d_out;

    float *ln1, *qkv, *att, *x1, *ln2, *up, *wa, *wp, *wu, *wd;
    cudaGetSymbolAddress((void**)&ln1, g_ln1);
    cudaGetSymbolAddress((void**)&qkv, g_qkv);
    cudaGetSymbolAddress((void**)&att, g_att);
    cudaGetSymbolAddress((void**)&x1,  g_x1);
    cudaGetSymbolAddress((void**)&ln2, g_ln2);
    cudaGetSymbolAddress((void**)&up,  g_up);
    cudaGetSymbolAddress((void**)&wa,  g_wattn);
    cudaGetSymbolAddress((void**)&wp,  g_wproj);
    cudaGetSymbolAddress((void**)&wu,  g_wup);
    cudaGetSymbolAddress((void**)&wd,  g_wdown);

    cudaFuncSetAttribute((const void*)gemm_mma<false, false, false>,
                         cudaFuncAttributeMaxDynamicSharedMemorySize, SMEM_BYTES);
    cudaFuncSetAttribute((const void*)gemm_mma<false, true, false>,
                         cudaFuncAttributeMaxDynamicSharedMemorySize, SMEM_BYTES);
    cudaFuncSetAttribute((const void*)gemm_mma<true, false, true>,
                         cudaFuncAttributeMaxDynamicSharedMemorySize, SMEM_BYTES);

    // round weights to tf32 (RN)
    cvt_tf32_kernel<<<3072, 256>>>((const float4*)W_attn, (float4*)wa, 786432);
    cvt_tf32_kernel<<<1024, 256>>>((const float4*)W_proj, (float4*)wp, 262144);
    cvt_tf32_kernel<<<4096, 256>>>((const float4*)W_up,   (float4*)wu, 1048576);
    cvt_tf32_kernel<<<4096, 256>>>((const float4*)W_down, (float4*)wd, 1048576);

    // 1. LN1
    ln_kernel<<<4096, 256>>>(x, ln1_g, ln1_b, ln1);
    // 2. QKV
    gemm_mma<false, false, false><<<dim3(3072 / BN, 4096 / BM), 256, SMEM_BYTES>>>(
        ln1, wa, b_attn, nullptr, qkv, 4096, 3072, 1024);
    // 3. attention
    attn_kernel<<<dim3(16, 16, 2), 128>>>(qkv, att);
    // 4. x1 = x + att @ W_proj^T + b_proj
    gemm_mma<false, true, false><<<dim3(1024 / BN, 4096 / BM), 256, SMEM_BYTES>>>(
        att, wp, b_proj, x, x1, 4096, 1024, 1024);
    // 5. LN2
    ln_kernel<<<4096, 256>>>(x1, ln2_g, ln2_b, ln2);
    // 6. up = round(gelu(ln2 @ W_up^T + b_up))
    gemm_mma<true, false, true><<<dim3(4096 / BN, 4096 / BM), 256, SMEM_BYTES>>>(
        ln2, wu, b_up, nullptr, up, 4096, 4096, 1024);
    // 7. out = x1 + up @ W_down^T + b_down
    gemm_mma<false, true, false><<<dim3(1024 / BN, 4096 / BM), 256, SMEM_BYTES>>>(
        up, wd, b_down, x1, out, 4096, 1024, 4096);
}

// round 4
// speedup vs baseline: 8.2971x; 3.4485x over previous
#include <cuda_runtime.h>
#include <cuda_fp16.h>
#include <math.h>
#include <stdint.h>

// ===================== scratch (device globals; no alloc allowed) ===========
__device__ __half g_ln1[4096 * 1024];
__device__ __half g_qkv[4096 * 3072];
__device__ __half g_att[4096 * 1024];
__device__ float  g_x1 [4096 * 1024];
__device__ __half g_ln2[4096 * 1024];
__device__ __half g_up [4096 * 4096];
__device__ __half g_wattn[3 * 1024 * 1024];
__device__ __half g_wproj[1024 * 1024];
__device__ __half g_wup  [4 * 1024 * 1024];
__device__ __half g_wdown[4 * 1024 * 1024];

// ===================== helpers ==============================================
__device__ __forceinline__ uint32_t packh2(float a, float b) {
    __half2 h = __floats2half2_rn(a, b);
    return *reinterpret_cast<uint32_t*>(&h);
}

__device__ __forceinline__ void cp16(uint32_t saddr, const void* g) {
    asm volatile("cp.async.cg.shared.global [%0], [%1], 16;"
                 :: "r"(saddr), "l"(__cvta_generic_to_global(g)));
}

__device__ __forceinline__ void ldsm4(uint32_t* r, uint32_t addr) {
    asm volatile("ldmatrix.sync.aligned.m8n8.x4.shared.b16 {%0,%1,%2,%3}, [%4];"
                 : "=r"(r[0]), "=r"(r[1]), "=r"(r[2]), "=r"(r[3]) : "r"(addr));
}

__device__ __forceinline__ void ldsm4t(uint32_t* r, uint32_t addr) {
    asm volatile("ldmatrix.sync.aligned.m8n8.x4.trans.shared.b16 {%0,%1,%2,%3}, [%4];"
                 : "=r"(r[0]), "=r"(r[1]), "=r"(r[2]), "=r"(r[3]) : "r"(addr));
}

__device__ __forceinline__ void mma_f16(float* d, const uint32_t* a, const uint32_t* b) {
    asm volatile("mma.sync.aligned.m16n8k16.row.col.f32.f16.f16.f32 "
                 "{%0,%1,%2,%3}, {%4,%5,%6,%7}, {%8,%9}, {%0,%1,%2,%3};"
                 : "+f"(d[0]), "+f"(d[1]), "+f"(d[2]), "+f"(d[3])
                 : "r"(a[0]), "r"(a[1]), "r"(a[2]), "r"(a[3]), "r"(b[0]), "r"(b[1]));
}

__device__ __forceinline__ float gelu_f(float t) {
    return 0.5f * t * (1.f + tanhf(0.7978845608028654f * (t + 0.044715f * t * t * t)));
}

__device__ __forceinline__ uint32_t swz(uint32_t row, uint32_t chunk, uint32_t xr) {
    return row * 128 + (((chunk) ^ xr) << 4);
}

// ===================== fp16 weight converter ================================
__global__ __launch_bounds__(256) void cvt_h_kernel(const float4* __restrict__ in,
                                                    uint2* __restrict__ out, int n4) {
    int i = blockIdx.x * 256 + threadIdx.x;
    if (i < n4) {
        float4 v = in[i];
        uint2 o;
        o.x = packh2(v.x, v.y);
        o.y = packh2(v.z, v.w);
        out[i] = o;
    }
}

// ===================== LayerNorm (fp32 in -> fp16 out) ======================
__global__ __launch_bounds__(256) void ln_kernel(const float* __restrict__ x,
                                                 const float* __restrict__ g,
                                                 const float* __restrict__ b,
                                                 __half* __restrict__ y) {
    int row = blockIdx.x;
    int tid = threadIdx.x;
    const float4* xr = (const float4*)(x + (size_t)row * 1024);
    float4 v = xr[tid];
    float s  = v.x + v.y + v.z + v.w;
    float sq = v.x * v.x + v.y * v.y + v.z * v.z + v.w * v.w;
    #pragma unroll
    for (int off = 16; off; off >>= 1) {
        s  += __shfl_xor_sync(0xFFFFFFFFu, s,  off);
        sq += __shfl_xor_sync(0xFFFFFFFFu, sq, off);
    }
    __shared__ float ss[8], ssq[8];
    int w = tid >> 5, ln = tid & 31;
    if (ln == 0) { ss[w] = s; ssq[w] = sq; }
    __syncthreads();
    float tot = 0.f, totq = 0.f;
    #pragma unroll
    for (int i = 0; i < 8; i++) { tot += ss[i]; totq += ssq[i]; }
    float mu   = tot * (1.f / 1024.f);
    float var  = totq * (1.f / 1024.f) - mu * mu;
    float rstd = rsqrtf(var + 1e-5f);
    float4 gg = ((const float4*)g)[tid];
    float4 bb = ((const float4*)b)[tid];
    uint2 o;
    o.x = packh2((v.x - mu) * rstd * gg.x + bb.x, (v.y - mu) * rstd * gg.y + bb.y);
    o.y = packh2((v.z - mu) * rstd * gg.z + bb.z, (v.w - mu) * rstd * gg.w + bb.w);
    *(uint2*)(y + (size_t)row * 1024 + tid * 4) = o;
}

// ===================== fp16 mma GEMM ========================================
// C[M,N] = A[M,K] @ B[N,K]^T (+bias)(+res)(gelu); A,B fp16; C fp32 or fp16.
// CTA: 128x128 tile, KC=64 halfs (128B rows), 256 threads, warp tile 64x32.
#define BM 128
#define BN 128
#define KC 64
#define SM_BUF 16384
#define SMEM_BYTES (4 * SM_BUF)

template <bool GELU, bool RES, bool OUTH>
__global__ __launch_bounds__(256, 2) void gemm_h(
    const __half* __restrict__ A, const __half* __restrict__ B,
    const float* __restrict__ bias, const float* __restrict__ res,
    void* __restrict__ Cv, int M, int N, int K)
{
    extern __shared__ char smem[];
    uint32_t sbase = (uint32_t)__cvta_generic_to_shared(smem);
    uint32_t sA[2] = { sbase,              sbase + SM_BUF };
    uint32_t sB[2] = { sbase + 2 * SM_BUF, sbase + 3 * SM_BUF };

    int tid  = threadIdx.x;
    int warp = tid >> 5, lane = tid & 31;
    int m0 = blockIdx.y * BM, n0 = blockIdx.x * BN;
    int wm = (warp & 1) * 64;
    int wn = (warp >> 1) * 32;

    int mat = lane >> 3, rowIn = lane & 7;
    int rA = wm + rowIn + 8 * (mat & 1);
    int cA = mat >> 1;
    int rB = wn + rowIn + 8 * (mat >> 1);
    int cB = mat & 1;

    uint32_t offA[4]; const __half* gA[4];
    uint32_t offB[4]; const __half* gB[4];
    #pragma unroll
    for (int t = 0; t < 4; t++) {
        int idx = tid + t * 256;
        int r = idx >> 3, c = idx & 7;
        uint32_t o = swz(r, c, r & 7);
        offA[t] = o; offB[t] = o;
        gA[t] = A + (size_t)(m0 + r) * K + c * 8;
        gB[t] = B + (size_t)(n0 + r) * K + c * 8;
    }

    float acc[4][4][4];
    #pragma unroll
    for (int i = 0; i < 4; i++)
        #pragma unroll
        for (int j = 0; j < 4; j++)
            #pragma unroll
            for (int e = 0; e < 4; e++) acc[i][j][e] = 0.f;

    int NC = K / KC;

    #pragma unroll
    for (int t = 0; t < 4; t++) cp16(sA[0] + offA[t], gA[t]);
    #pragma unroll
    for (int t = 0; t < 4; t++) cp16(sB[0] + offB[t], gB[t]);
    asm volatile("cp.async.commit_group;" ::: "memory");

    for (int c = 0; c < NC; c++) {
        int buf = c & 1;
        if (c + 1 < NC) {
            int koff = (c + 1) * KC;
            #pragma unroll
            for (int t = 0; t < 4; t++) cp16(sA[buf ^ 1] + offA[t], gA[t] + koff);
            #pragma unroll
            for (int t = 0; t < 4; t++) cp16(sB[buf ^ 1] + offB[t], gB[t] + koff);
            asm volatile("cp.async.commit_group;" ::: "memory");
            asm volatile("cp.async.wait_group 1;" ::: "memory");
        } else {
            asm volatile("cp.async.wait_group 0;" ::: "memory");
        }
        __syncthreads();

        uint32_t bA = sA[buf], bB = sB[buf];
        #pragma unroll
        for (int ks = 0; ks < 4; ks++) {
            uint32_t af[4][4], bf[2][4];
            #pragma unroll
            for (int i = 0; i < 4; i++)
                ldsm4(af[i], bA + swz((uint32_t)(rA + 16 * i), (uint32_t)(ks * 2 + cA), (uint32_t)rowIn));
            #pragma unroll
            for (int p = 0; p < 2; p++)
                ldsm4(bf[p], bB + swz((uint32_t)(rB + 16 * p), (uint32_t)(ks * 2 + cB), (uint32_t)rowIn));
            #pragma unroll
            for (int i = 0; i < 4; i++) {
                #pragma unroll
                for (int j = 0; j < 4; j++) {
                    uint32_t bb[2] = { bf[j >> 1][(j & 1) * 2], bf[j >> 1][(j & 1) * 2 + 1] };
                    mma_f16(acc[i][j], af[i], bb);
                }
            }
        }
        __syncthreads();
    }

    // epilogue
    float*  Cf = (float*)Cv;
    __half* Ch = (__half*)Cv;
    #pragma unroll
    for (int i = 0; i < 4; i++) {
        int gr = m0 + wm + i * 16 + (lane >> 2);
        #pragma unroll
        for (int j = 0; j < 4; j++) {
            int gc = n0 + wn + j * 8 + (lane & 3) * 2;
            float2 bv = *(const float2*)(bias + gc);
            float v0 = acc[i][j][0] + bv.x, v1 = acc[i][j][1] + bv.y;
            float v2 = acc[i][j][2] + bv.x, v3 = acc[i][j][3] + bv.y;
            if (RES) {
                float2 r0 = *(const float2*)(res + (size_t)gr * N + gc);
                float2 r1 = *(const float2*)(res + (size_t)(gr + 8) * N + gc);
                v0 += r0.x; v1 += r0.y; v2 += r1.x; v3 += r1.y;
            }
            if (GELU) { v0 = gelu_f(v0); v1 = gelu_f(v1); v2 = gelu_f(v2); v3 = gelu_f(v3); }
            if (OUTH) {
                *(uint32_t*)(Ch + (size_t)gr * N + gc)       = packh2(v0, v1);
                *(uint32_t*)(Ch + (size_t)(gr + 8) * N + gc) = packh2(v2, v3);
            } else {
                *(float2*)(Cf + (size_t)gr * N + gc)       = make_float2(v0, v1);
                *(float2*)(Cf + (size_t)(gr + 8) * N + gc) = make_float2(v2, v3);
            }
        }
    }
}

// ===================== fp16 mma flash attention =============================
// Block: 256 thr (8 warps), 128 queries of one (b,h). Warp owns 16 q rows.
// Key tiles of 64. S=Q@K^T via mma; P kept in registers; O += P@V via
// ldmatrix.trans on naturally-stored V.
__global__ __launch_bounds__(256) void attn_mma(const __half* __restrict__ qkv,
                                                __half* __restrict__ att) {
    __shared__ char smem_raw[32768];  // Q 16K | K 8K | V 8K
    uint32_t sbase = (uint32_t)__cvta_generic_to_shared(smem_raw);
    uint32_t sQ = sbase, sK = sbase + 16384, sV = sbase + 24576;

    int tid = threadIdx.x;
    int warp = tid >> 5, lane = tid & 31;
    int qb = blockIdx.x, h = blockIdx.y, bb = blockIdx.z;
    int q0 = qb * 128;
    int wq = warp * 16;
    int mat = lane >> 3, rowIn = lane & 7;

    const __half* base = qkv + (size_t)bb * 2048 * 3072;

    // load Q tile: 128 rows x 8 chunks
    #pragma unroll
    for (int t = 0; t < 4; t++) {
        int idx = tid + t * 256;
        int r = idx >> 3, c = idx & 7;
        cp16(sQ + swz(r, c, r & 7), base + (size_t)(q0 + r) * 3072 + h * 64 + c * 8);
    }
    asm volatile("cp.async.commit_group;" ::: "memory");
    asm volatile("cp.async.wait_group 0;" ::: "memory");
    __syncthreads();

    // preload Q fragments (k = 64 dims -> 4 ksteps)
    uint32_t qf[4][4];
    #pragma unroll
    for (int ks = 0; ks < 4; ks++)
        ldsm4(qf[ks], sQ + swz((uint32_t)(wq + rowIn + 8 * (mat & 1)),
                               (uint32_t)(ks * 2 + (mat >> 1)), (uint32_t)rowIn));

    float oacc[8][4];
    #pragma unroll
    for (int j = 0; j < 8; j++)
        #pragma unroll
        for (int e = 0; e < 4; e++) oacc[j][e] = 0.f;
    float m0v = -1e30f, m1v = -1e30f, l0 = 0.f, l1 = 0.f;

    int r_lo = lane >> 2;
    int row0g = q0 + wq + r_lo;        // global q row for c0,c1
    int row1g = row0g + 8;             // for c2,c3
    int colq = 2 * (lane & 3);

    int nt = 2 * qb + 2;
    for (int t = 0; t < nt; t++) {
        int ko = t * 64;
        __syncthreads();
        #pragma unroll
        for (int s = 0; s < 2; s++) {
            int idx = tid + s * 256;
            int r = idx >> 3, c = idx & 7;
            const __half* krow = base + (size_t)(ko + r) * 3072 + 1024 + h * 64 + c * 8;
            const __half* vrow = base + (size_t)(ko + r) * 3072 + 2048 + h * 64 + c * 8;
            cp16(sK + swz(r, c, r & 7), krow);
            cp16(sV + swz(r, c, r & 7), vrow);
        }
        asm volatile("cp.async.commit_group;" ::: "memory");
        asm volatile("cp.async.wait_group 0;" ::: "memory");
        __syncthreads();

        // ---- S = Q @ K^T  (128x64 tile; warp: 16x64) ----
        float sacc[8][4];
        #pragma unroll
        for (int j = 0; j < 8; j++)
            #pragma unroll
            for (int e = 0; e < 4; e++) sacc[j][e] = 0.f;
        #pragma unroll
        for (int ks = 0; ks < 4; ks++) {
            uint32_t kf[4][4];
            #pragma unroll
            for (int p = 0; p < 4; p++)
                ldsm4(kf[p], sK + swz((uint32_t)(p * 16 + rowIn + 8 * (mat >> 1)),
                                      (uint32_t)(ks * 2 + (mat & 1)), (uint32_t)rowIn));
            #pragma unroll
            for (int j = 0; j < 8; j++) {
                uint32_t bb2[2] = { kf[j >> 1][(j & 1) * 2], kf[j >> 1][(j & 1) * 2 + 1] };
                mma_f16(sacc[j], qf[ks], bb2);
            }
        }

        // ---- scale + causal mask ----
        bool diag = (t >= 2 * qb);
        #pragma unroll
        for (int j = 0; j < 8; j++) {
            #pragma unroll
            for (int e = 0; e < 4; e++) sacc[j][e] *= 0.125f;
            if (diag) {
                int c0 = ko + 8 * j + colq, c1 = c0 + 1;
                if (c0 > row0g) sacc[j][0] = -1e30f;
                if (c1 > row0g) sacc[j][1] = -1e30f;
                if (c0 > row1g) sacc[j][2] = -1e30f;
                if (c1 > row1g) sacc[j][3] = -1e30f;
            }
        }

        // ---- online softmax (row stats across 4-lane quad) ----
        float tm0 = -1e30f, tm1 = -1e30f;
        #pragma unroll
        for (int j = 0; j < 8; j++) {
            tm0 = fmaxf(tm0, fmaxf(sacc[j][0], sacc[j][1]));
            tm1 = fmaxf(tm1, fmaxf(sacc[j][2], sacc[j][3]));
        }
        #pragma unroll
        for (int off = 1; off <= 2; off <<= 1) {
            tm0 = fmaxf(tm0, __shfl_xor_sync(0xFFFFFFFFu, tm0, off));
            tm1 = fmaxf(tm1, __shfl_xor_sync(0xFFFFFFFFu, tm1, off));
        }
        float mn0 = fmaxf(m0v, tm0), mn1 = fmaxf(m1v, tm1);
        float corr0 = __expf(m0v - mn0), corr1 = __expf(m1v - mn1);

        uint32_t ph[8][2];
        float ps0 = 0.f, ps1 = 0.f;
        #pragma unroll
        for (int j = 0; j < 8; j++) {
            float p0 = __expf(sacc[j][0] - mn0);
            float p1 = __expf(sacc[j][1] - mn0);
            float p2 = __expf(sacc[j][2] - mn1);
            float p3 = __expf(sacc[j][3] - mn1);
            ps0 += p0 + p1; ps1 += p2 + p3;
            ph[j][0] = packh2(p0, p1);
            ph[j][1] = packh2(p2, p3);
        }
        #pragma unroll
        for (int off = 1; off <= 2; off <<= 1) {
            ps0 += __shfl_xor_sync(0xFFFFFFFFu, ps0, off);
            ps1 += __shfl_xor_sync(0xFFFFFFFFu, ps1, off);
        }
        l0 = l0 * corr0 + ps0;
        l1 = l1 * corr1 + ps1;
        #pragma unroll
        for (int j = 0; j < 8; j++) {
            oacc[j][0] *= corr0; oacc[j][1] *= corr0;
            oacc[j][2] *= corr1; oacc[j][3] *= corr1;
        }
        m0v = mn0; m1v = mn1;

        // ---- O += P @ V  (keys = k dim; V via ldmatrix.trans) ----
        #pragma unroll
        for (int ks = 0; ks < 4; ks++) {
            uint32_t vf[4][4];
            #pragma unroll
            for (int p = 0; p < 4; p++)
                ldsm4t(vf[p], sV + swz((uint32_t)(ks * 16 + rowIn + 8 * (mat & 1)),
                                       (uint32_t)(p * 2 + (mat >> 1)), (uint32_t)rowIn));
            uint32_t af[4] = { ph[2 * ks][0], ph[2 * ks][1], ph[2 * ks + 1][0], ph[2 * ks + 1][1] };
            #pragma unroll
            for (int j = 0; j < 8; j++) {
                uint32_t bb2[2] = { vf[j >> 1][(j & 1) * 2], vf[j >> 1][(j & 1) * 2 + 1] };
                mma_f16(oacc[j], af, bb2);
            }
        }
    }

    // ---- finalize + store fp16 ----
    float inv0 = 1.f / l0, inv1 = 1.f / l1;
    size_t obase0 = ((size_t)bb * 2048 + row0g) * 1024 + h * 64;
    size_t obase1 = ((size_t)bb * 2048 + row1g) * 1024 + h * 64;
    #pragma unroll
    for (int j = 0; j < 8; j++) {
        int col = 8 * j + colq;
        *(uint32_t*)(att + obase0 + col) = packh2(oacc[j][0] * inv0, oacc[j][1] * inv0);
        *(uint32_t*)(att + obase1 + col) = packh2(oacc[j][2] * inv1, oacc[j][3] * inv1);
    }
}

// ===================== launch ===============================================
extern "C" void kernel_launch(void* const* d_in, const int* in_sizes, int n_in,
                              void* d_out, int out_size) {
    const float* x      = (const float*)d_in[0];
    const float* ln1_g  = (const float*)d_in[1];
    const float* ln1_b  = (const float*)d_in[2];
    const float* W_attn = (const float*)d_in[3];
    const float* b_attn = (const float*)d_in[4];
    const float* W_proj = (const float*)d_in[5];
    const float* b_proj = (const float*)d_in[6];
    const float* ln2_g  = (const float*)d_in[7];
    const float* ln2_b  = (const float*)d_in[8];
    const float* W_up   = (const float*)d_in[9];
    const float* b_up   = (const float*)d_in[10];
    const float* W_down = (const float*)d_in[11];
    const float* b_down = (const float*)d_in[12];
    float* out = (float*)d_out;

    __half *ln1, *qkv, *att, *ln2, *up, *wa, *wp, *wu, *wd;
    float  *x1;
    cudaGetSymbolAddress((void**)&ln1, g_ln1);
    cudaGetSymbolAddress((void**)&qkv, g_qkv);
    cudaGetSymbolAddress((void**)&att, g_att);
    cudaGetSymbolAddress((void**)&x1,  g_x1);
    cudaGetSymbolAddress((void**)&ln2, g_ln2);
    cudaGetSymbolAddress((void**)&up,  g_up);
    cudaGetSymbolAddress((void**)&wa,  g_wattn);
    cudaGetSymbolAddress((void**)&wp,  g_wproj);
    cudaGetSymbolAddress((void**)&wu,  g_wup);
    cudaGetSymbolAddress((void**)&wd,  g_wdown);

    cudaFuncSetAttribute((const void*)gemm_h<false, false, true>,
                         cudaFuncAttributeMaxDynamicSharedMemorySize, SMEM_BYTES);
    cudaFuncSetAttribute((const void*)gemm_h<false, true, false>,
                         cudaFuncAttributeMaxDynamicSharedMemorySize, SMEM_BYTES);
    cudaFuncSetAttribute((const void*)gemm_h<true, false, true>,
                         cudaFuncAttributeMaxDynamicSharedMemorySize, SMEM_BYTES);

    // weights fp32 -> fp16
    cvt_h_kernel<<<3072, 256>>>((const float4*)W_attn, (uint2*)wa, 786432);
    cvt_h_kernel<<<1024, 256>>>((const float4*)W_proj, (uint2*)wp, 262144);
    cvt_h_kernel<<<4096, 256>>>((const float4*)W_up,   (uint2*)wu, 1048576);
    cvt_h_kernel<<<4096, 256>>>((const float4*)W_down, (uint2*)wd, 1048576);

    // 1. LN1
    ln_kernel<<<4096, 256>>>(x, ln1_g, ln1_b, ln1);
    // 2. QKV = ln1 @ W_attn^T + b_attn  (fp16 out)
    gemm_h<false, false, true><<<dim3(3072 / BN, 4096 / BM), 256, SMEM_BYTES>>>(
        ln1, wa, b_attn, nullptr, qkv, 4096, 3072, 1024);
    // 3. attention (fp16 mma flash)
    attn_mma<<<dim3(16, 16, 2), 256>>>(qkv, att);
    // 4. x1 = x + att @ W_proj^T + b_proj  (fp32 out)
    gemm_h<false, true, false><<<dim3(1024 / BN, 4096 / BM), 256, SMEM_BYTES>>>(
        att, wp, b_proj, x, x1, 4096, 1024, 1024);
    // 5. LN2
    ln_kernel<<<4096, 256>>>(x1, ln2_g, ln2_b, ln2);
    // 6. up = gelu(ln2 @ W_up^T + b_up)  (fp16 out)
    gemm_h<true, false, true><<<dim3(4096 / BN, 4096 / BM), 256, SMEM_BYTES>>>(
        ln2, wu, b_up, nullptr, up, 4096, 4096, 1024);
    // 7. out = x1 + up @ W_down^T + b_down  (fp32 out)
    gemm_h<false, true, false><<<dim3(1024 / BN, 4096 / BM), 256, SMEM_BYTES>>>(
        up, wd, b_down, x1, out, 4096, 1024, 4096);
}

// round 5
// speedup vs baseline: 8.8354x; 1.0649x over previous
#include <cuda_runtime.h>
#include <cuda_fp16.h>
#include <math.h>
#include <stdint.h>

// ===================== scratch (device globals; no alloc allowed) ===========
__device__ __half g_ln1[4096 * 1024];
__device__ __half g_qkv[4096 * 3072];
__device__ __half g_att[4096 * 1024];
__device__ float  g_x1 [4096 * 1024];
__device__ __half g_ln2[4096 * 1024];
__device__ __half g_up [4096 * 4096];
__device__ __half g_wattn[3 * 1024 * 1024];
__device__ __half g_wproj[1024 * 1024];
__device__ __half g_wup  [4 * 1024 * 1024];
__device__ __half g_wdown[4 * 1024 * 1024];

// ===================== helpers ==============================================
__device__ __forceinline__ uint32_t packh2(float a, float b) {
    __half2 h = __floats2half2_rn(a, b);
    return *reinterpret_cast<uint32_t*>(&h);
}

__device__ __forceinline__ void cp16(uint32_t saddr, const void* g) {
    asm volatile("cp.async.cg.shared.global [%0], [%1], 16;"
                 :: "r"(saddr), "l"(__cvta_generic_to_global(g)));
}

__device__ __forceinline__ void ldsm4(uint32_t* r, uint32_t addr) {
    asm volatile("ldmatrix.sync.aligned.m8n8.x4.shared.b16 {%0,%1,%2,%3}, [%4];"
                 : "=r"(r[0]), "=r"(r[1]), "=r"(r[2]), "=r"(r[3]) : "r"(addr));
}

__device__ __forceinline__ void ldsm4t(uint32_t* r, uint32_t addr) {
    asm volatile("ldmatrix.sync.aligned.m8n8.x4.trans.shared.b16 {%0,%1,%2,%3}, [%4];"
                 : "=r"(r[0]), "=r"(r[1]), "=r"(r[2]), "=r"(r[3]) : "r"(addr));
}

__device__ __forceinline__ void mma_f16(float* d, const uint32_t* a, const uint32_t* b) {
    asm volatile("mma.sync.aligned.m16n8k16.row.col.f32.f16.f16.f32 "
                 "{%0,%1,%2,%3}, {%4,%5,%6,%7}, {%8,%9}, {%0,%1,%2,%3};"
                 : "+f"(d[0]), "+f"(d[1]), "+f"(d[2]), "+f"(d[3])
                 : "r"(a[0]), "r"(a[1]), "r"(a[2]), "r"(a[3]), "r"(b[0]), "r"(b[1]));
}

__device__ __forceinline__ float tanh_ap(float x) {
    float y;
    asm("tanh.approx.f32 %0, %1;" : "=f"(y) : "f"(x));
    return y;
}

__device__ __forceinline__ float gelu_f(float t) {
    return 0.5f * t * (1.f + tanh_ap(0.7978845608028654f * (t + 0.044715f * t * t * t)));
}

__device__ __forceinline__ uint32_t swz(uint32_t row, uint32_t chunk, uint32_t xr) {
    return row * 128 + (((chunk) ^ xr) << 4);
}

// ===================== fused fp16 weight converter ==========================
// segments (float4 counts): wa 786432 | wp 262144 | wu 1048576 | wd 1048576
__global__ __launch_bounds__(256) void cvt_all_kernel(
    const float4* __restrict__ wa_in, const float4* __restrict__ wp_in,
    const float4* __restrict__ wu_in, const float4* __restrict__ wd_in,
    uint2* __restrict__ wa_o, uint2* __restrict__ wp_o,
    uint2* __restrict__ wu_o, uint2* __restrict__ wd_o)
{
    int i = blockIdx.x * 256 + threadIdx.x;  // < 3145728
    const float4* src; uint2* dst; int off;
    if (i < 786432)       { src = wa_in; dst = wa_o; off = i; }
    else if (i < 1048576) { src = wp_in; dst = wp_o; off = i - 786432; }
    else if (i < 2097152) { src = wu_in; dst = wu_o; off = i - 1048576; }
    else                  { src = wd_in; dst = wd_o; off = i - 2097152; }
    float4 v = src[off];
    uint2 o;
    o.x = packh2(v.x, v.y);
    o.y = packh2(v.z, v.w);
    dst[off] = o;
}

// ===================== LayerNorm (fp32 in -> fp16 out) ======================
__global__ __launch_bounds__(256) void ln_kernel(const float* __restrict__ x,
                                                 const float* __restrict__ g,
                                                 const float* __restrict__ b,
                                                 __half* __restrict__ y) {
    int row = blockIdx.x;
    int tid = threadIdx.x;
    const float4* xr = (const float4*)(x + (size_t)row * 1024);
    float4 v = xr[tid];
    float s  = v.x + v.y + v.z + v.w;
    float sq = v.x * v.x + v.y * v.y + v.z * v.z + v.w * v.w;
    #pragma unroll
    for (int off = 16; off; off >>= 1) {
        s  += __shfl_xor_sync(0xFFFFFFFFu, s,  off);
        sq += __shfl_xor_sync(0xFFFFFFFFu, sq, off);
    }
    __shared__ float ss[8], ssq[8];
    int w = tid >> 5, ln = tid & 31;
    if (ln == 0) { ss[w] = s; ssq[w] = sq; }
    __syncthreads();
    float tot = 0.f, totq = 0.f;
    #pragma unroll
    for (int i = 0; i < 8; i++) { tot += ss[i]; totq += ssq[i]; }
    float mu   = tot * (1.f / 1024.f);
    float var  = totq * (1.f / 1024.f) - mu * mu;
    float rstd = rsqrtf(var + 1e-5f);
    float4 gg = ((const float4*)g)[tid];
    float4 bb = ((const float4*)b)[tid];
    uint2 o;
    o.x = packh2((v.x - mu) * rstd * gg.x + bb.x, (v.y - mu) * rstd * gg.y + bb.y);
    o.y = packh2((v.z - mu) * rstd * gg.z + bb.z, (v.w - mu) * rstd * gg.w + bb.w);
    *(uint2*)(y + (size_t)row * 1024 + tid * 4) = o;
}

// ===================== fp16 mma GEMM ========================================
// C[M,N] = A[M,K] @ B[N,K]^T (+bias)(+res)(gelu); A,B fp16; C fp32 or fp16.
// CTA 128x128, KC=64 halfs (128B rows), 256 thr, warp tile 64x32.
// Single-barrier double-buffered cp.async pipeline.
#define BM 128
#define BN 128
#define KC 64
#define SM_BUF 16384
#define SMEM_BYTES (4 * SM_BUF)

template <bool GELU, bool RES, bool OUTH>
__global__ __launch_bounds__(256, 2) void gemm_h(
    const __half* __restrict__ A, const __half* __restrict__ B,
    const float* __restrict__ bias, const float* __restrict__ res,
    void* __restrict__ Cv, int M, int N, int K)
{
    extern __shared__ char smem[];
    uint32_t sbase = (uint32_t)__cvta_generic_to_shared(smem);
    uint32_t sA[2] = { sbase,              sbase + SM_BUF };
    uint32_t sB[2] = { sbase + 2 * SM_BUF, sbase + 3 * SM_BUF };

    int tid  = threadIdx.x;
    int warp = tid >> 5, lane = tid & 31;
    int m0 = blockIdx.y * BM, n0 = blockIdx.x * BN;
    int wm = (warp & 1) * 64;
    int wn = (warp >> 1) * 32;

    int mat = lane >> 3, rowIn = lane & 7;
    int rA = wm + rowIn + 8 * (mat & 1);
    int cA = mat >> 1;
    int rB = wn + rowIn + 8 * (mat >> 1);
    int cB = mat & 1;

    uint32_t offA[4]; const __half* gA[4];
    uint32_t offB[4]; const __half* gB[4];
    #pragma unroll
    for (int t = 0; t < 4; t++) {
        int idx = tid + t * 256;
        int r = idx >> 3, c = idx & 7;
        uint32_t o = swz(r, c, r & 7);
        offA[t] = o; offB[t] = o;
        gA[t] = A + (size_t)(m0 + r) * K + c * 8;
        gB[t] = B + (size_t)(n0 + r) * K + c * 8;
    }

    float acc[4][4][4];
    #pragma unroll
    for (int i = 0; i < 4; i++)
        #pragma unroll
        for (int j = 0; j < 4; j++)
            #pragma unroll
            for (int e = 0; e < 4; e++) acc[i][j][e] = 0.f;

    int NC = K / KC;

    // prologue: chunk 0 -> buf 0
    #pragma unroll
    for (int t = 0; t < 4; t++) cp16(sA[0] + offA[t], gA[t]);
    #pragma unroll
    for (int t = 0; t < 4; t++) cp16(sB[0] + offB[t], gB[t]);
    asm volatile("cp.async.commit_group;" ::: "memory");
    asm volatile("cp.async.wait_group 0;" ::: "memory");
    __syncthreads();

    for (int c = 0; c < NC; c++) {
        int buf = c & 1;
        // prefetch next chunk (safe: last barrier covered all reads of buf^1)
        if (c + 1 < NC) {
            int koff = (c + 1) * KC;
            #pragma unroll
            for (int t = 0; t < 4; t++) cp16(sA[buf ^ 1] + offA[t], gA[t] + koff);
            #pragma unroll
            for (int t = 0; t < 4; t++) cp16(sB[buf ^ 1] + offB[t], gB[t] + koff);
            asm volatile("cp.async.commit_group;" ::: "memory");
        }

        uint32_t bA = sA[buf], bB = sB[buf];
        #pragma unroll
        for (int ks = 0; ks < 4; ks++) {
            uint32_t af[4][4], bf[2][4];
            #pragma unroll
            for (int i = 0; i < 4; i++)
                ldsm4(af[i], bA + swz((uint32_t)(rA + 16 * i), (uint32_t)(ks * 2 + cA), (uint32_t)rowIn));
            #pragma unroll
            for (int p = 0; p < 2; p++)
                ldsm4(bf[p], bB + swz((uint32_t)(rB + 16 * p), (uint32_t)(ks * 2 + cB), (uint32_t)rowIn));
            #pragma unroll
            for (int i = 0; i < 4; i++) {
                #pragma unroll
                for (int j = 0; j < 4; j++) {
                    uint32_t bb[2] = { bf[j >> 1][(j & 1) * 2], bf[j >> 1][(j & 1) * 2 + 1] };
                    mma_f16(acc[i][j], af[i], bb);
                }
            }
        }

        if (c + 1 < NC) {
            asm volatile("cp.async.wait_group 0;" ::: "memory");
            __syncthreads();
        }
    }

    // epilogue
    float*  Cf = (float*)Cv;
    __half* Ch = (__half*)Cv;
    #pragma unroll
    for (int i = 0; i < 4; i++) {
        int gr = m0 + wm + i * 16 + (lane >> 2);
        #pragma unroll
        for (int j = 0; j < 4; j++) {
            int gc = n0 + wn + j * 8 + (lane & 3) * 2;
            float2 bv = *(const float2*)(bias + gc);
            float v0 = acc[i][j][0] + bv.x, v1 = acc[i][j][1] + bv.y;
            float v2 = acc[i][j][2] + bv.x, v3 = acc[i][j][3] + bv.y;
            if (RES) {
                float2 r0 = *(const float2*)(res + (size_t)gr * N + gc);
                float2 r1 = *(const float2*)(res + (size_t)(gr + 8) * N + gc);
                v0 += r0.x; v1 += r0.y; v2 += r1.x; v3 += r1.y;
            }
            if (GELU) { v0 = gelu_f(v0); v1 = gelu_f(v1); v2 = gelu_f(v2); v3 = gelu_f(v3); }
            if (OUTH) {
                *(uint32_t*)(Ch + (size_t)gr * N + gc)       = packh2(v0, v1);
                *(uint32_t*)(Ch + (size_t)(gr + 8) * N + gc) = packh2(v2, v3);
            } else {
                *(float2*)(Cf + (size_t)gr * N + gc)       = make_float2(v0, v1);
                *(float2*)(Cf + (size_t)(gr + 8) * N + gc) = make_float2(v2, v3);
            }
        }
    }
}

// ===================== fp16 mma flash attention =============================
// 256 thr (8 warps) per 128 queries of one (b,h); warp owns 16 q rows.
// K/V tiles of 64 double-buffered via cp.async; one barrier per tile.
__global__ __launch_bounds__(256) void attn_mma(const __half* __restrict__ qkv,
                                                __half* __restrict__ att) {
    __shared__ char smem_raw[49152];  // Q 16K | K 2x8K | V 2x8K
    uint32_t sbase = (uint32_t)__cvta_generic_to_shared(smem_raw);
    uint32_t sQ = sbase;
    uint32_t sKst[2] = { sbase + 16384, sbase + 24576 };
    uint32_t sVst[2] = { sbase + 32768, sbase + 40960 };

    int tid = threadIdx.x;
    int warp = tid >> 5, lane = tid & 31;
    int qb = blockIdx.x, h = blockIdx.y, bb = blockIdx.z;
    int q0 = qb * 128;
    int wq = warp * 16;
    int mat = lane >> 3, rowIn = lane & 7;

    const __half* base = qkv + (size_t)bb * 2048 * 3072;

    // KV loader slots (64 rows x 8 chunks per tile; 2/thread each for K and V)
    int nt = 2 * qb + 2;
    auto load_kv = [&](int t, int st) {
        int ko = t * 64;
        #pragma unroll
        for (int s = 0; s < 2; s++) {
            int idx = tid + s * 256;
            int r = idx >> 3, c = idx & 7;
            uint32_t o = swz(r, c, r & 7);
            const __half* krow = base + (size_t)(ko + r) * 3072 + 1024 + h * 64 + c * 8;
            const __half* vrow = base + (size_t)(ko + r) * 3072 + 2048 + h * 64 + c * 8;
            cp16(sKst[st] + o, krow);
            cp16(sVst[st] + o, vrow);
        }
    };

    // prologue: Q + KV tile 0
    #pragma unroll
    for (int t = 0; t < 4; t++) {
        int idx = tid + t * 256;
        int r = idx >> 3, c = idx & 7;
        cp16(sQ + swz(r, c, r & 7), base + (size_t)(q0 + r) * 3072 + h * 64 + c * 8);
    }
    load_kv(0, 0);
    asm volatile("cp.async.commit_group;" ::: "memory");
    asm volatile("cp.async.wait_group 0;" ::: "memory");
    __syncthreads();

    // preload Q fragments, fold in softmax scale 1/8 (exact in fp16)
    uint32_t qf[4][4];
    const uint32_t h125 = 0x30003000u;  // half2(0.125, 0.125)
    #pragma unroll
    for (int ks = 0; ks < 4; ks++) {
        ldsm4(qf[ks], sQ + swz((uint32_t)(wq + rowIn + 8 * (mat & 1)),
                               (uint32_t)(ks * 2 + (mat >> 1)), (uint32_t)rowIn));
        #pragma unroll
        for (int i = 0; i < 4; i++)
            asm("mul.f16x2 %0, %0, %1;" : "+r"(qf[ks][i]) : "r"(h125));
    }

    float oacc[8][4];
    #pragma unroll
    for (int j = 0; j < 8; j++)
        #pragma unroll
        for (int e = 0; e < 4; e++) oacc[j][e] = 0.f;
    float m0v = -1e30f, m1v = -1e30f, l0 = 0.f, l1 = 0.f;

    int r_lo = lane >> 2;
    int row0g = q0 + wq + r_lo;
    int row1g = row0g + 8;
    int colq = 2 * (lane & 3);

    for (int t = 0; t < nt; t++) {
        int st = t & 1;
        int ko = t * 64;
        if (t + 1 < nt) {
            load_kv(t + 1, st ^ 1);
            asm volatile("cp.async.commit_group;" ::: "memory");
        }

        // ---- S = Q @ K^T ----
        float sacc[8][4];
        #pragma unroll
        for (int j = 0; j < 8; j++)
            #pragma unroll
            for (int e = 0; e < 4; e++) sacc[j][e] = 0.f;
        #pragma unroll
        for (int ks = 0; ks < 4; ks++) {
            uint32_t kf[4][4];
            #pragma unroll
            for (int p = 0; p < 4; p++)
                ldsm4(kf[p], sKst[st] + swz((uint32_t)(p * 16 + rowIn + 8 * (mat >> 1)),
                                            (uint32_t)(ks * 2 + (mat & 1)), (uint32_t)rowIn));
            #pragma unroll
            for (int j = 0; j < 8; j++) {
                uint32_t bb2[2] = { kf[j >> 1][(j & 1) * 2], kf[j >> 1][(j & 1) * 2 + 1] };
                mma_f16(sacc[j], qf[ks], bb2);
            }
        }

        // ---- causal mask ----
        if (t >= 2 * qb) {
            #pragma unroll
            for (int j = 0; j < 8; j++) {
                int c0 = ko + 8 * j + colq, c1 = c0 + 1;
                if (c0 > row0g) sacc[j][0] = -1e30f;
                if (c1 > row0g) sacc[j][1] = -1e30f;
                if (c0 > row1g) sacc[j][2] = -1e30f;
                if (c1 > row1g) sacc[j][3] = -1e30f;
            }
        }

        // ---- online softmax (stats across 4-lane quad) ----
        float tm0 = -1e30f, tm1 = -1e30f;
        #pragma unroll
        for (int j = 0; j < 8; j++) {
            tm0 = fmaxf(tm0, fmaxf(sacc[j][0], sacc[j][1]));
            tm1 = fmaxf(tm1, fmaxf(sacc[j][2], sacc[j][3]));
        }
        #pragma unroll
        for (int off = 1; off <= 2; off <<= 1) {
            tm0 = fmaxf(tm0, __shfl_xor_sync(0xFFFFFFFFu, tm0, off));
            tm1 = fmaxf(tm1, __shfl_xor_sync(0xFFFFFFFFu, tm1, off));
        }
        float mn0 = fmaxf(m0v, tm0), mn1 = fmaxf(m1v, tm1);
        float corr0 = __expf(m0v - mn0), corr1 = __expf(m1v - mn1);

        uint32_t ph[8][2];
        float ps0 = 0.f, ps1 = 0.f;
        #pragma unroll
        for (int j = 0; j < 8; j++) {
            float p0 = __expf(sacc[j][0] - mn0);
            float p1 = __expf(sacc[j][1] - mn0);
            float p2 = __expf(sacc[j][2] - mn1);
            float p3 = __expf(sacc[j][3] - mn1);
            ps0 += p0 + p1; ps1 += p2 + p3;
            ph[j][0] = packh2(p0, p1);
            ph[j][1] = packh2(p2, p3);
        }
        #pragma unroll
        for (int off = 1; off <= 2; off <<= 1) {
            ps0 += __shfl_xor_sync(0xFFFFFFFFu, ps0, off);
            ps1 += __shfl_xor_sync(0xFFFFFFFFu, ps1, off);
        }
        l0 = l0 * corr0 + ps0;
        l1 = l1 * corr1 + ps1;
        #pragma unroll
        for (int j = 0; j < 8; j++) {
            oacc[j][0] *= corr0; oacc[j][1] *= corr0;
            oacc[j][2] *= corr1; oacc[j][3] *= corr1;
        }
        m0v = mn0; m1v = mn1;

        // ---- O += P @ V ----
        #pragma unroll
        for (int ks = 0; ks < 4; ks++) {
            uint32_t vf[4][4];
            #pragma unroll
            for (int p = 0; p < 4; p++)
                ldsm4t(vf[p], sVst[st] + swz((uint32_t)(ks * 16 + rowIn + 8 * (mat & 1)),
                                             (uint32_t)(p * 2 + (mat >> 1)), (uint32_t)rowIn));
            uint32_t af[4] = { ph[2 * ks][0], ph[2 * ks][1], ph[2 * ks + 1][0], ph[2 * ks + 1][1] };
            #pragma unroll
            for (int j = 0; j < 8; j++) {
                uint32_t bb2[2] = { vf[j >> 1][(j & 1) * 2], vf[j >> 1][(j & 1) * 2 + 1] };
                mma_f16(oacc[j], af, bb2);
            }
        }

        if (t + 1 < nt) {
            asm volatile("cp.async.wait_group 0;" ::: "memory");
            __syncthreads();
        }
    }

    // ---- finalize + store fp16 ----
    float inv0 = 1.f / l0, inv1 = 1.f / l1;
    size_t obase0 = ((size_t)bb * 2048 + row0g) * 1024 + h * 64;
    size_t obase1 = ((size_t)bb * 2048 + row1g) * 1024 + h * 64;
    #pragma unroll
    for (int j = 0; j < 8; j++) {
        int col = 8 * j + colq;
        *(uint32_t*)(att + obase0 + col) = packh2(oacc[j][0] * inv0, oacc[j][1] * inv0);
        *(uint32_t*)(att + obase1 + col) = packh2(oacc[j][2] * inv1, oacc[j][3] * inv1);
    }
}

// ===================== launch ===============================================
extern "C" void kernel_launch(void* const* d_in, const int* in_sizes, int n_in,
                              void* d_out, int out_size) {
    const float* x      = (const float*)d_in[0];
    const float* ln1_g  = (const float*)d_in[1];
    const float* ln1_b  = (const float*)d_in[2];
    const float* W_attn = (const float*)d_in[3];
    const float* b_attn = (const float*)d_in[4];
    const float* W_proj = (const float*)d_in[5];
    const float* b_proj = (const float*)d_in[6];
    const float* ln2_g  = (const float*)d_in[7];
    const float* ln2_b  = (const float*)d_in[8];
    const float* W_up   = (const float*)d_in[9];
    const float* b_up   = (const float*)d_in[10];
    const float* W_down = (const float*)d_in[11];
    const float* b_down = (const float*)d_in[12];
    float* out = (float*)d_out;

    __half *ln1, *qkv, *att, *ln2, *up, *wa, *wp, *wu, *wd;
    float  *x1;
    cudaGetSymbolAddress((void**)&ln1, g_ln1);
    cudaGetSymbolAddress((void**)&qkv, g_qkv);
    cudaGetSymbolAddress((void**)&att, g_att);
    cudaGetSymbolAddress((void**)&x1,  g_x1);
    cudaGetSymbolAddress((void**)&ln2, g_ln2);
    cudaGetSymbolAddress((void**)&up,  g_up);
    cudaGetSymbolAddress((void**)&wa,  g_wattn);
    cudaGetSymbolAddress((void**)&wp,  g_wproj);
    cudaGetSymbolAddress((void**)&wu,  g_wup);
    cudaGetSymbolAddress((void**)&wd,  g_wdown);

    cudaFuncSetAttribute((const void*)gemm_h<false, false, true>,
                         cudaFuncAttributeMaxDynamicSharedMemorySize, SMEM_BYTES);
    cudaFuncSetAttribute((const void*)gemm_h<false, true, false>,
                         cudaFuncAttributeMaxDynamicSharedMemorySize, SMEM_BYTES);
    cudaFuncSetAttribute((const void*)gemm_h<true, false, true>,
                         cudaFuncAttributeMaxDynamicSharedMemorySize, SMEM_BYTES);

    // all weights fp32 -> fp16 in one launch
    cvt_all_kernel<<<12288, 256>>>((const float4*)W_attn, (const float4*)W_proj,
                                   (const float4*)W_up,   (const float4*)W_down,
                                   (uint2*)wa, (uint2*)wp, (uint2*)wu, (uint2*)wd);

    // 1. LN1
    ln_kernel<<<4096, 256>>>(x, ln1_g, ln1_b, ln1);
    // 2. QKV = ln1 @ W_attn^T + b_attn  (fp16 out)
    gemm_h<false, false, true><<<dim3(3072 / BN, 4096 / BM), 256, SMEM_BYTES>>>(
        ln1, wa, b_attn, nullptr, qkv, 4096, 3072, 1024);
    // 3. attention (fp16 mma flash)
    attn_mma<<<dim3(16, 16, 2), 256>>>(qkv, att);
    // 4. x1 = x + att @ W_proj^T + b_proj  (fp32 out)
    gemm_h<false, true, false><<<dim3(1024 / BN, 4096 / BM), 256, SMEM_BYTES>>>(
        att, wp, b_proj, x, x1, 4096, 1024, 1024);
    // 5. LN2
    ln_kernel<<<4096, 256>>>(x1, ln2_g, ln2_b, ln2);
    // 6. up = gelu(ln2 @ W_up^T + b_up)  (fp16 out)
    gemm_h<true, false, true><<<dim3(4096 / BN, 4096 / BM), 256, SMEM_BYTES>>>(
        ln2, wu, b_up, nullptr, up, 4096, 4096, 1024);
    // 7. out = x1 + up @ W_down^T + b_down  (fp32 out)
    gemm_h<false, true, false><<<dim3(1024 / BN, 4096 / BM), 256, SMEM_BYTES>>>(
        up, wd, b_down, x1, out, 4096, 1024, 4096);
}

// round 6
// speedup vs baseline: 8.9825x; 1.0166x over previous
#include <cuda_runtime.h>
#include <cuda_fp16.h>
#include <math.h>
#include <stdint.h>

// ===================== scratch (device globals; no alloc allowed) ===========
__device__ __half g_ln1[4096 * 1024];
__device__ __half g_qkv[4096 * 3072];
__device__ __half g_att[4096 * 1024];
__device__ float  g_x1 [4096 * 1024];
__device__ __half g_ln2[4096 * 1024];
__device__ __half g_up [4096 * 4096];
__device__ __half g_wattn[3 * 1024 * 1024];
__device__ __half g_wproj[1024 * 1024];
__device__ __half g_wup  [4 * 1024 * 1024];
__device__ __half g_wdown[4 * 1024 * 1024];

// ===================== helpers ==============================================
__device__ __forceinline__ uint32_t packh2(float a, float b) {
    __half2 h = __floats2half2_rn(a, b);
    return *reinterpret_cast<uint32_t*>(&h);
}

__device__ __forceinline__ void cp16(uint32_t saddr, const void* g) {
    asm volatile("cp.async.cg.shared.global [%0], [%1], 16;"
                 :: "r"(saddr), "l"(__cvta_generic_to_global(g)));
}

__device__ __forceinline__ void ldsm4(uint32_t* r, uint32_t addr) {
    asm volatile("ldmatrix.sync.aligned.m8n8.x4.shared.b16 {%0,%1,%2,%3}, [%4];"
                 : "=r"(r[0]), "=r"(r[1]), "=r"(r[2]), "=r"(r[3]) : "r"(addr));
}

__device__ __forceinline__ void ldsm4t(uint32_t* r, uint32_t addr) {
    asm volatile("ldmatrix.sync.aligned.m8n8.x4.trans.shared.b16 {%0,%1,%2,%3}, [%4];"
                 : "=r"(r[0]), "=r"(r[1]), "=r"(r[2]), "=r"(r[3]) : "r"(addr));
}

__device__ __forceinline__ void mma_f16(float* d, const uint32_t* a, const uint32_t* b) {
    asm volatile("mma.sync.aligned.m16n8k16.row.col.f32.f16.f16.f32 "
                 "{%0,%1,%2,%3}, {%4,%5,%6,%7}, {%8,%9}, {%0,%1,%2,%3};"
                 : "+f"(d[0]), "+f"(d[1]), "+f"(d[2]), "+f"(d[3])
                 : "r"(a[0]), "r"(a[1]), "r"(a[2]), "r"(a[3]), "r"(b[0]), "r"(b[1]));
}

__device__ __forceinline__ float tanh_ap(float x) {
    float y;
    asm("tanh.approx.f32 %0, %1;" : "=f"(y) : "f"(x));
    return y;
}

__device__ __forceinline__ float gelu_f(float t) {
    return 0.5f * t * (1.f + tanh_ap(0.7978845608028654f * (t + 0.044715f * t * t * t)));
}

__device__ __forceinline__ uint32_t swz(uint32_t row, uint32_t chunk, uint32_t xr) {
    return row * 128 + (((chunk) ^ xr) << 4);
}

// ===================== fused fp16 weight converter ==========================
__global__ __launch_bounds__(256) void cvt_all_kernel(
    const float4* __restrict__ wa_in, const float4* __restrict__ wp_in,
    const float4* __restrict__ wu_in, const float4* __restrict__ wd_in,
    uint2* __restrict__ wa_o, uint2* __restrict__ wp_o,
    uint2* __restrict__ wu_o, uint2* __restrict__ wd_o)
{
    int i = blockIdx.x * 256 + threadIdx.x;  // < 3145728
    const float4* src; uint2* dst; int off;
    if (i < 786432)       { src = wa_in; dst = wa_o; off = i; }
    else if (i < 1048576) { src = wp_in; dst = wp_o; off = i - 786432; }
    else if (i < 2097152) { src = wu_in; dst = wu_o; off = i - 1048576; }
    else                  { src = wd_in; dst = wd_o; off = i - 2097152; }
    float4 v = src[off];
    uint2 o;
    o.x = packh2(v.x, v.y);
    o.y = packh2(v.z, v.w);
    dst[off] = o;
}

// ===================== LayerNorm (fp32 in -> fp16 out) ======================
__global__ __launch_bounds__(256) void ln_kernel(const float* __restrict__ x,
                                                 const float* __restrict__ g,
                                                 const float* __restrict__ b,
                                                 __half* __restrict__ y) {
    int row = blockIdx.x;
    int tid = threadIdx.x;
    const float4* xr = (const float4*)(x + (size_t)row * 1024);
    float4 v = xr[tid];
    float s  = v.x + v.y + v.z + v.w;
    float sq = v.x * v.x + v.y * v.y + v.z * v.z + v.w * v.w;
    #pragma unroll
    for (int off = 16; off; off >>= 1) {
        s  += __shfl_xor_sync(0xFFFFFFFFu, s,  off);
        sq += __shfl_xor_sync(0xFFFFFFFFu, sq, off);
    }
    __shared__ float ss[8], ssq[8];
    int w = tid >> 5, ln = tid & 31;
    if (ln == 0) { ss[w] = s; ssq[w] = sq; }
    __syncthreads();
    float tot = 0.f, totq = 0.f;
    #pragma unroll
    for (int i = 0; i < 8; i++) { tot += ss[i]; totq += ssq[i]; }
    float mu   = tot * (1.f / 1024.f);
    float var  = totq * (1.f / 1024.f) - mu * mu;
    float rstd = rsqrtf(var + 1e-5f);
    float4 gg = ((const float4*)g)[tid];
    float4 bb = ((const float4*)b)[tid];
    uint2 o;
    o.x = packh2((v.x - mu) * rstd * gg.x + bb.x, (v.y - mu) * rstd * gg.y + bb.y);
    o.y = packh2((v.z - mu) * rstd * gg.z + bb.z, (v.w - mu) * rstd * gg.w + bb.w);
    *(uint2*)(y + (size_t)row * 1024 + tid * 4) = o;
}

// ===================== fp16 mma GEMM (3-stage cp.async ring) ================
// C[M,N] = A[M,K] @ B[N,K]^T (+bias)(+res)(gelu); A,B fp16; C fp32 or fp16.
// CTA 128x128, KC=64 halfs, 256 thr, warp tile 64x32, 3-stage smem ring.
#define BM 128
#define BN 128
#define KC 64
#define SM_TILE 16384
#define SMEM_BYTES (6 * SM_TILE)

template <bool GELU, bool RES, bool OUTH>
__global__ __launch_bounds__(256, 2) void gemm_h(
    const __half* __restrict__ A, const __half* __restrict__ B,
    const float* __restrict__ bias, const float* __restrict__ res,
    void* __restrict__ Cv, int M, int N, int K)
{
    extern __shared__ char smem[];
    uint32_t sbase = (uint32_t)__cvta_generic_to_shared(smem);
    uint32_t sA[3] = { sbase, sbase + SM_TILE, sbase + 2 * SM_TILE };
    uint32_t sB[3] = { sbase + 3 * SM_TILE, sbase + 4 * SM_TILE, sbase + 5 * SM_TILE };

    int tid  = threadIdx.x;
    int warp = tid >> 5, lane = tid & 31;
    int m0 = blockIdx.y * BM, n0 = blockIdx.x * BN;
    int wm = (warp & 1) * 64;
    int wn = (warp >> 1) * 32;

    int mat = lane >> 3, rowIn = lane & 7;
    int rA = wm + rowIn + 8 * (mat & 1);
    int cA = mat >> 1;
    int rB = wn + rowIn + 8 * (mat >> 1);
    int cB = mat & 1;

    uint32_t offT[4]; const __half* gA[4]; const __half* gB[4];
    #pragma unroll
    for (int t = 0; t < 4; t++) {
        int idx = tid + t * 256;
        int r = idx >> 3, c = idx & 7;
        offT[t] = swz(r, c, r & 7);
        gA[t] = A + (size_t)(m0 + r) * K + c * 8;
        gB[t] = B + (size_t)(n0 + r) * K + c * 8;
    }

    float acc[4][4][4];
    #pragma unroll
    for (int i = 0; i < 4; i++)
        #pragma unroll
        for (int j = 0; j < 4; j++)
            #pragma unroll
            for (int e = 0; e < 4; e++) acc[i][j][e] = 0.f;

    int NC = K / KC;

    // prologue: chunks 0,1 -> bufs 0,1
    #pragma unroll
    for (int t = 0; t < 4; t++) cp16(sA[0] + offT[t], gA[t]);
    #pragma unroll
    for (int t = 0; t < 4; t++) cp16(sB[0] + offT[t], gB[t]);
    asm volatile("cp.async.commit_group;" ::: "memory");
    #pragma unroll
    for (int t = 0; t < 4; t++) cp16(sA[1] + offT[t], gA[t] + KC);
    #pragma unroll
    for (int t = 0; t < 4; t++) cp16(sB[1] + offT[t], gB[t] + KC);
    asm volatile("cp.async.commit_group;" ::: "memory");
    asm volatile("cp.async.wait_group 1;" ::: "memory");
    __syncthreads();

    int cbuf = 0, lbuf = 2;
    for (int c = 0; c < NC; c++) {
        if (c + 2 < NC) {
            int koff = (c + 2) * KC;
            #pragma unroll
            for (int t = 0; t < 4; t++) cp16(sA[lbuf] + offT[t], gA[t] + koff);
            #pragma unroll
            for (int t = 0; t < 4; t++) cp16(sB[lbuf] + offT[t], gB[t] + koff);
            asm volatile("cp.async.commit_group;" ::: "memory");
        }

        uint32_t bA = sA[cbuf], bB = sB[cbuf];
        #pragma unroll
        for (int ks = 0; ks < 4; ks++) {
            uint32_t af[4][4], bf[2][4];
            #pragma unroll
            for (int i = 0; i < 4; i++)
                ldsm4(af[i], bA + swz((uint32_t)(rA + 16 * i), (uint32_t)(ks * 2 + cA), (uint32_t)rowIn));
            #pragma unroll
            for (int p = 0; p < 2; p++)
                ldsm4(bf[p], bB + swz((uint32_t)(rB + 16 * p), (uint32_t)(ks * 2 + cB), (uint32_t)rowIn));
            #pragma unroll
            for (int i = 0; i < 4; i++) {
                #pragma unroll
                for (int j = 0; j < 4; j++) {
                    uint32_t bb[2] = { bf[j >> 1][(j & 1) * 2], bf[j >> 1][(j & 1) * 2 + 1] };
                    mma_f16(acc[i][j], af[i], bb);
                }
            }
        }

        if (c + 1 < NC) {
            if (c + 2 < NC) { asm volatile("cp.async.wait_group 1;" ::: "memory"); }
            else            { asm volatile("cp.async.wait_group 0;" ::: "memory"); }
            __syncthreads();
        }
        cbuf = (cbuf == 2) ? 0 : cbuf + 1;
        lbuf = (lbuf == 2) ? 0 : lbuf + 1;
    }

    // epilogue
    float*  Cf = (float*)Cv;
    __half* Ch = (__half*)Cv;
    #pragma unroll
    for (int i = 0; i < 4; i++) {
        int gr = m0 + wm + i * 16 + (lane >> 2);
        #pragma unroll
        for (int j = 0; j < 4; j++) {
            int gc = n0 + wn + j * 8 + (lane & 3) * 2;
            float2 bv = *(const float2*)(bias + gc);
            float v0 = acc[i][j][0] + bv.x, v1 = acc[i][j][1] + bv.y;
            float v2 = acc[i][j][2] + bv.x, v3 = acc[i][j][3] + bv.y;
            if (RES) {
                float2 r0 = *(const float2*)(res + (size_t)gr * N + gc);
                float2 r1 = *(const float2*)(res + (size_t)(gr + 8) * N + gc);
                v0 += r0.x; v1 += r0.y; v2 += r1.x; v3 += r1.y;
            }
            if (GELU) { v0 = gelu_f(v0); v1 = gelu_f(v1); v2 = gelu_f(v2); v3 = gelu_f(v3); }
            if (OUTH) {
                *(uint32_t*)(Ch + (size_t)gr * N + gc)       = packh2(v0, v1);
                *(uint32_t*)(Ch + (size_t)(gr + 8) * N + gc) = packh2(v2, v3);
            } else {
                *(float2*)(Cf + (size_t)gr * N + gc)       = make_float2(v0, v1);
                *(float2*)(Cf + (size_t)(gr + 8) * N + gc) = make_float2(v2, v3);
            }
        }
    }
}

// ===================== fp16 mma flash attention (work-paired) ===============
// Grid (8, 16, 2); CTA processes qb = 15-bx then qb = bx -> uniform 34 tiles.
__global__ __launch_bounds__(256) void attn_mma(const __half* __restrict__ qkv,
                                                __half* __restrict__ att) {
    __shared__ char smem_raw[49152];  // Q 16K | K 2x8K | V 2x8K
    uint32_t sbase = (uint32_t)__cvta_generic_to_shared(smem_raw);
    uint32_t sQ = sbase;
    uint32_t sKst[2] = { sbase + 16384, sbase + 24576 };
    uint32_t sVst[2] = { sbase + 32768, sbase + 40960 };

    int tid = threadIdx.x;
    int warp = tid >> 5, lane = tid & 31;
    int h = blockIdx.y, bb = blockIdx.z;
    int wq = warp * 16;
    int mat = lane >> 3, rowIn = lane & 7;

    const __half* base = qkv + (size_t)bb * 2048 * 3072;
    const uint32_t h125 = 0x30003000u;  // half2(0.125, 0.125)

    int r_lo = lane >> 2;
    int colq = 2 * (lane & 3);

    #pragma unroll
    for (int pass = 0; pass < 2; pass++) {
        int qb = pass == 0 ? (15 - (int)blockIdx.x) : (int)blockIdx.x;
        int q0 = qb * 128;
        int nt = 2 * qb + 2;

        __syncthreads();  // smem reuse across passes

        // load Q tile + KV tile 0
        #pragma unroll
        for (int t = 0; t < 4; t++) {
            int idx = tid + t * 256;
            int r = idx >> 3, c = idx & 7;
            cp16(sQ + swz(r, c, r & 7), base + (size_t)(q0 + r) * 3072 + h * 64 + c * 8);
        }
        #pragma unroll
        for (int s = 0; s < 2; s++) {
            int idx = tid + s * 256;
            int r = idx >> 3, c = idx & 7;
            uint32_t o = swz(r, c, r & 7);
            cp16(sKst[0] + o, base + (size_t)r * 3072 + 1024 + h * 64 + c * 8);
            cp16(sVst[0] + o, base + (size_t)r * 3072 + 2048 + h * 64 + c * 8);
        }
        asm volatile("cp.async.commit_group;" ::: "memory");
        asm volatile("cp.async.wait_group 0;" ::: "memory");
        __syncthreads();

        // preload Q fragments with folded 1/8 scale
        uint32_t qf[4][4];
        #pragma unroll
        for (int ks = 0; ks < 4; ks++) {
            ldsm4(qf[ks], sQ + swz((uint32_t)(wq + rowIn + 8 * (mat & 1)),
                                   (uint32_t)(ks * 2 + (mat >> 1)), (uint32_t)rowIn));
            #pragma unroll
            for (int i = 0; i < 4; i++)
                asm("mul.f16x2 %0, %0, %1;" : "+r"(qf[ks][i]) : "r"(h125));
        }

        float oacc[8][4];
        #pragma unroll
        for (int j = 0; j < 8; j++)
            #pragma unroll
            for (int e = 0; e < 4; e++) oacc[j][e] = 0.f;
        float m0v = -1e30f, m1v = -1e30f, l0 = 0.f, l1 = 0.f;

        int row0g = q0 + wq + r_lo;
        int row1g = row0g + 8;

        for (int t = 0; t < nt; t++) {
            int st = t & 1;
            int ko = t * 64;
            if (t + 1 < nt) {
                int ko2 = (t + 1) * 64;
                #pragma unroll
                for (int s = 0; s < 2; s++) {
                    int idx = tid + s * 256;
                    int r = idx >> 3, c = idx & 7;
                    uint32_t o = swz(r, c, r & 7);
                    cp16(sKst[st ^ 1] + o, base + (size_t)(ko2 + r) * 3072 + 1024 + h * 64 + c * 8);
                    cp16(sVst[st ^ 1] + o, base + (size_t)(ko2 + r) * 3072 + 2048 + h * 64 + c * 8);
                }
                asm volatile("cp.async.commit_group;" ::: "memory");
            }

            // ---- S = Q @ K^T ----
            float sacc[8][4];
            #pragma unroll
            for (int j = 0; j < 8; j++)
                #pragma unroll
                for (int e = 0; e < 4; e++) sacc[j][e] = 0.f;
            #pragma unroll
            for (int ks = 0; ks < 4; ks++) {
                uint32_t kf[4][4];
                #pragma unroll
                for (int p = 0; p < 4; p++)
                    ldsm4(kf[p], sKst[st] + swz((uint32_t)(p * 16 + rowIn + 8 * (mat >> 1)),
                                                (uint32_t)(ks * 2 + (mat & 1)), (uint32_t)rowIn));
                #pragma unroll
                for (int j = 0; j < 8; j++) {
                    uint32_t bb2[2] = { kf[j >> 1][(j & 1) * 2], kf[j >> 1][(j & 1) * 2 + 1] };
                    mma_f16(sacc[j], qf[ks], bb2);
                }
            }

            // ---- causal mask ----
            if (t >= 2 * qb) {
                #pragma unroll
                for (int j = 0; j < 8; j++) {
                    int c0 = ko + 8 * j + colq, c1 = c0 + 1;
                    if (c0 > row0g) sacc[j][0] = -1e30f;
                    if (c1 > row0g) sacc[j][1] = -1e30f;
                    if (c0 > row1g) sacc[j][2] = -1e30f;
                    if (c1 > row1g) sacc[j][3] = -1e30f;
                }
            }

            // ---- online softmax ----
            float tm0 = -1e30f, tm1 = -1e30f;
            #pragma unroll
            for (int j = 0; j < 8; j++) {
                tm0 = fmaxf(tm0, fmaxf(sacc[j][0], sacc[j][1]));
                tm1 = fmaxf(tm1, fmaxf(sacc[j][2], sacc[j][3]));
            }
            #pragma unroll
            for (int off = 1; off <= 2; off <<= 1) {
                tm0 = fmaxf(tm0, __shfl_xor_sync(0xFFFFFFFFu, tm0, off));
                tm1 = fmaxf(tm1, __shfl_xor_sync(0xFFFFFFFFu, tm1, off));
            }
            float mn0 = fmaxf(m0v, tm0), mn1 = fmaxf(m1v, tm1);
            float corr0 = __expf(m0v - mn0), corr1 = __expf(m1v - mn1);

            uint32_t ph[8][2];
            float ps0 = 0.f, ps1 = 0.f;
            #pragma unroll
            for (int j = 0; j < 8; j++) {
                float p0 = __expf(sacc[j][0] - mn0);
                float p1 = __expf(sacc[j][1] - mn0);
                float p2 = __expf(sacc[j][2] - mn1);
                float p3 = __expf(sacc[j][3] - mn1);
                ps0 += p0 + p1; ps1 += p2 + p3;
                ph[j][0] = packh2(p0, p1);
                ph[j][1] = packh2(p2, p3);
            }
            #pragma unroll
            for (int off = 1; off <= 2; off <<= 1) {
                ps0 += __shfl_xor_sync(0xFFFFFFFFu, ps0, off);
                ps1 += __shfl_xor_sync(0xFFFFFFFFu, ps1, off);
            }
            l0 = l0 * corr0 + ps0;
            l1 = l1 * corr1 + ps1;
            #pragma unroll
            for (int j = 0; j < 8; j++) {
                oacc[j][0] *= corr0; oacc[j][1] *= corr0;
                oacc[j][2] *= corr1; oacc[j][3] *= corr1;
            }
            m0v = mn0; m1v = mn1;

            // ---- O += P @ V ----
            #pragma unroll
            for (int ks = 0; ks < 4; ks++) {
                uint32_t vf[4][4];
                #pragma unroll
                for (int p = 0; p < 4; p++)
                    ldsm4t(vf[p], sVst[st] + swz((uint32_t)(ks * 16 + rowIn + 8 * (mat & 1)),
                                                 (uint32_t)(p * 2 + (mat >> 1)), (uint32_t)rowIn));
                uint32_t af[4] = { ph[2 * ks][0], ph[2 * ks][1], ph[2 * ks + 1][0], ph[2 * ks + 1][1] };
                #pragma unroll
                for (int j = 0; j < 8; j++) {
                    uint32_t bb2[2] = { vf[j >> 1][(j & 1) * 2], vf[j >> 1][(j & 1) * 2 + 1] };
                    mma_f16(oacc[j], af, bb2);
                }
            }

            if (t + 1 < nt) {
                asm volatile("cp.async.wait_group 0;" ::: "memory");
                __syncthreads();
            }
        }

        // ---- finalize + store fp16 ----
        float inv0 = 1.f / l0, inv1 = 1.f / l1;
        size_t obase0 = ((size_t)bb * 2048 + row0g) * 1024 + h * 64;
        size_t obase1 = ((size_t)bb * 2048 + row1g) * 1024 + h * 64;
        #pragma unroll
        for (int j = 0; j < 8; j++) {
            int col = 8 * j + colq;
            *(uint32_t*)(att + obase0 + col) = packh2(oacc[j][0] * inv0, oacc[j][1] * inv0);
            *(uint32_t*)(att + obase1 + col) = packh2(oacc[j][2] * inv1, oacc[j][3] * inv1);
        }
    }
}

// ===================== launch ===============================================
extern "C" void kernel_launch(void* const* d_in, const int* in_sizes, int n_in,
                              void* d_out, int out_size) {
    const float* x      = (const float*)d_in[0];
    const float* ln1_g  = (const float*)d_in[1];
    const float* ln1_b  = (const float*)d_in[2];
    const float* W_attn = (const float*)d_in[3];
    const float* b_attn = (const float*)d_in[4];
    const float* W_proj = (const float*)d_in[5];
    const float* b_proj = (const float*)d_in[6];
    const float* ln2_g  = (const float*)d_in[7];
    const float* ln2_b  = (const float*)d_in[8];
    const float* W_up   = (const float*)d_in[9];
    const float* b_up   = (const float*)d_in[10];
    const float* W_down = (const float*)d_in[11];
    const float* b_down = (const float*)d_in[12];
    float* out = (float*)d_out;

    __half *ln1, *qkv, *att, *ln2, *up, *wa, *wp, *wu, *wd;
    float  *x1;
    cudaGetSymbolAddress((void**)&ln1, g_ln1);
    cudaGetSymbolAddress((void**)&qkv, g_qkv);
    cudaGetSymbolAddress((void**)&att, g_att);
    cudaGetSymbolAddress((void**)&x1,  g_x1);
    cudaGetSymbolAddress((void**)&ln2, g_ln2);
    cudaGetSymbolAddress((void**)&up,  g_up);
    cudaGetSymbolAddress((void**)&wa,  g_wattn);
    cudaGetSymbolAddress((void**)&wp,  g_wproj);
    cudaGetSymbolAddress((void**)&wu,  g_wup);
    cudaGetSymbolAddress((void**)&wd,  g_wdown);

    cudaFuncSetAttribute((const void*)gemm_h<false, false, true>,
                         cudaFuncAttributeMaxDynamicSharedMemorySize, SMEM_BYTES);
    cudaFuncSetAttribute((const void*)gemm_h<false, true, false>,
                         cudaFuncAttributeMaxDynamicSharedMemorySize, SMEM_BYTES);
    cudaFuncSetAttribute((const void*)gemm_h<true, false, true>,
                         cudaFuncAttributeMaxDynamicSharedMemorySize, SMEM_BYTES);

    // all weights fp32 -> fp16 in one launch
    cvt_all_kernel<<<12288, 256>>>((const float4*)W_attn, (const float4*)W_proj,
                                   (const float4*)W_up,   (const float4*)W_down,
                                   (uint2*)wa, (uint2*)wp, (uint2*)wu, (uint2*)wd);

    // 1. LN1
    ln_kernel<<<4096, 256>>>(x, ln1_g, ln1_b, ln1);
    // 2. QKV = ln1 @ W_attn^T + b_attn  (fp16 out)
    gemm_h<false, false, true><<<dim3(3072 / BN, 4096 / BM), 256, SMEM_BYTES>>>(
        ln1, wa, b_attn, nullptr, qkv, 4096, 3072, 1024);
    // 3. attention (fp16 mma flash, work-paired)
    attn_mma<<<dim3(8, 16, 2), 256>>>(qkv, att);
    // 4. x1 = x + att @ W_proj^T + b_proj  (fp32 out)
    gemm_h<false, true, false><<<dim3(1024 / BN, 4096 / BM), 256, SMEM_BYTES>>>(
        att, wp, b_proj, x, x1, 4096, 1024, 1024);
    // 5. LN2
    ln_kernel<<<4096, 256>>>(x1, ln2_g, ln2_b, ln2);
    // 6. up = gelu(ln2 @ W_up^T + b_up)  (fp16 out)
    gemm_h<true, false, true><<<dim3(4096 / BN, 4096 / BM), 256, SMEM_BYTES>>>(
        ln2, wu, b_up, nullptr, up, 4096, 4096, 1024);
    // 7. out = x1 + up @ W_down^T + b_down  (fp32 out)
    gemm_h<false, true, false><<<dim3(1024 / BN, 4096 / BM), 256, SMEM_BYTES>>>(
        up, wd, b_down, x1, out, 4096, 1024, 4096);
}